// round 1
// baseline (speedup 1.0000x reference)
#include <cuda_runtime.h>
#include <math.h>

#define TTOK 49152      // total tokens = 2*6*64*64
#define NWIN 384        // windows  = 2*192
#define NH   8
#define HD   24
#define CCH  192

// ---------------- scratch (device globals; no allocations allowed) ----------
__device__ float g_xw[TTOK*192];        // LN1+shift+partition output (window order)
__device__ float g_qkv[TTOK*576];       // qkv (reused for self & mutual)
__device__ float g_xout[TTOK*384];      // concat([x1x2, x_self], ch)
__device__ float g_attnbuf[TTOK*192];   // proj output (window order)
__device__ float g_xres[TTOK*192];      // x + attn residual (original order)
__device__ float g_xn2[TTOK*192];       // LN2 output
__device__ float g_pos[64*192];         // sine pos encoding
__device__ float g_biasf[8*128*128];    // rel-pos bias per head, materialized
__device__ int   g_cnt[8];
__device__ int   g_gidx[8*TTOK];
__device__ float g_gw[8*TTOK];
__device__ int   g_grank[8*TTOK];
__device__ float g_contrib0[TTOK*192];
__device__ float g_contrib1[TTOK*192];

__device__ __forceinline__ float warpsum(float v) {
    #pragma unroll
    for (int o = 16; o; o >>= 1) v += __shfl_down_sync(0xffffffffu, v, o);
    return v;
}

// ---------------- prep: sine positional encoding + zero counters ------------
__global__ void k_pos() {
    int c = threadIdx.x;                 // 0..191
    if (c < 8) g_cnt[c] = 0;
    const float TWO_PI = 6.283185307179586f;
    const float denom = 8.0f + 1e-6f;
    int f = (c < 96) ? c : c - 96;
    float expo = (float)(f & ~1) / 96.0f;
    float dt = powf(10000.0f, expo);
    for (int n = 0; n < 64; n++) {
        int i = n >> 3, j = n & 7;
        float base = (c < 96) ? (float)(i + 1) : (float)(j + 1);
        float v = base / denom * TWO_PI / dt;
        g_pos[n*192 + c] = (f & 1) ? cosf(v) : sinf(v);
    }
}

// ---------------- prep: materialize rel-pos bias table ----------------------
__global__ void k_bias(const float* __restrict__ rpb) {
    int n = blockIdx.x, m = threadIdx.x;
    int dn = n >> 6, hn = (n >> 3) & 7, wn = n & 7;
    int dm = m >> 6, hm = (m >> 3) & 7, wm = m & 7;
    int rp = (dn - dm + 1)*225 + (hn - hm + 7)*15 + (wn - wm + 7);
    #pragma unroll
    for (int h = 0; h < 8; h++)
        g_biasf[h*16384 + n*128 + m] = rpb[rp*8 + h];
}

// ---------------- LN1 + roll(-1,-4,-4) + window partition --------------------
__global__ void ln_partition(const float* __restrict__ x,
                             const float* __restrict__ w1,
                             const float* __restrict__ b1) {
    int t = blockIdx.x;          // window-major token index: win*128 + n
    int c = threadIdx.x;         // 0..191
    int win = t >> 7, n = t & 127;
    int b_  = win / 192; int rem = win % 192;
    int dd  = rem / 64;  int rem2 = rem % 64;
    int hh  = rem2 >> 3; int ww = rem2 & 7;
    int wd  = n >> 6, wh = (n >> 3) & 7, wwp = n & 7;
    int ds = dd*2 + wd, hs = hh*8 + wh, ws = ww*8 + wwp;
    int d = ds + 1; if (d >= 6) d -= 6;          // shifted -> original
    int h = (hs + 4) & 63;
    int w = (ws + 4) & 63;
    size_t src = (size_t)(((b_*6 + d)*64 + h)*64 + w)*192 + c;
    float v = x[src];

    __shared__ float s1[6], s2[6];
    int wi = c >> 5, ln = c & 31;
    float a = warpsum(v), q = warpsum(v*v);
    if (ln == 0) { s1[wi] = a; s2[wi] = q; }
    __syncthreads();
    float S1 = 0.f, S2 = 0.f;
    #pragma unroll
    for (int i = 0; i < 6; i++) { S1 += s1[i]; S2 += s2[i]; }
    float mu  = S1 * (1.f/192.f);
    float var = S2 * (1.f/192.f) - mu*mu;
    g_xw[(size_t)t*192 + c] = (v - mu) * rsqrtf(var + 1e-5f) * w1[c] + b1[c];
}

// ---------------- generic tiled GEMM: C[T,N] = A[T,K] @ B[K,N] + bias --------
__global__ __launch_bounds__(256)
void gemm64(const float* __restrict__ A, const float* __restrict__ B,
            const float* __restrict__ bias, float* __restrict__ C,
            int K, int N, int add_pos) {
    __shared__ float  As[64][33];
    __shared__ float4 Bs[32][16];
    int row0 = blockIdx.x * 64, col0 = blockIdx.y * 64;
    int tid = threadIdx.x;
    int tx = tid & 15, ty = tid >> 4;
    float acc[4][4] = {};
    for (int kc = 0; kc < K; kc += 32) {
        int ar = tid >> 3;           // 0..31
        int ac = (tid & 7) * 4;
        #pragma unroll
        for (int it = 0; it < 2; it++) {
            int r = ar + it*32;
            float4 v = *reinterpret_cast<const float4*>(&A[(size_t)(row0 + r)*K + kc + ac]);
            if (add_pos) {
                const float4 p4 = *reinterpret_cast<const float4*>(
                    &g_pos[((row0 + r) & 63)*192 + kc + ac]);
                v.x += p4.x; v.y += p4.y; v.z += p4.z; v.w += p4.w;
            }
            As[r][ac+0] = v.x; As[r][ac+1] = v.y; As[r][ac+2] = v.z; As[r][ac+3] = v.w;
        }
        int br = tid >> 4, bc = tid & 15;
        #pragma unroll
        for (int it = 0; it < 2; it++) {
            int r = br + it*16;
            Bs[r][bc] = *reinterpret_cast<const float4*>(&B[(size_t)(kc + r)*N + col0 + bc*4]);
        }
        __syncthreads();
        #pragma unroll
        for (int kk = 0; kk < 32; kk++) {
            float4 b4 = Bs[kk][tx];
            #pragma unroll
            for (int i = 0; i < 4; i++) {
                float a = As[ty*4 + i][kk];
                acc[i][0] = fmaf(a, b4.x, acc[i][0]);
                acc[i][1] = fmaf(a, b4.y, acc[i][1]);
                acc[i][2] = fmaf(a, b4.z, acc[i][2]);
                acc[i][3] = fmaf(a, b4.w, acc[i][3]);
            }
        }
        __syncthreads();
    }
    #pragma unroll
    for (int i = 0; i < 4; i++) {
        size_t r = row0 + ty*4 + i;
        #pragma unroll
        for (int j = 0; j < 4; j++) {
            int cc = col0 + tx*4 + j;
            C[r*N + cc] = acc[i][j] + bias[cc];
        }
    }
}

// ---------------- self attention: one block per (window, head) --------------
__global__ void attn_self(const float* __restrict__ mask) {
    extern __shared__ float sm[];
    float* ks = sm;                 // 128*25
    float* vs = sm + 3200;          // 128*25
    float* sc = sm + 6400;          // 128*129
    int win = blockIdx.x >> 3, h = blockIdx.x & 7;
    int n = threadIdx.x;
    size_t base = (size_t)(win*128 + n)*576 + h*24;
    float q[24];
    #pragma unroll
    for (int d = 0; d < 24; d++) {
        q[d]          = g_qkv[base + d];
        ks[n*25 + d]  = g_qkv[base + 192 + d];
        vs[n*25 + d]  = g_qkv[base + 384 + d];
    }
    int mw = win % 192;
    const float* mrow = mask + (size_t)mw*16384;
    const float* brow = g_biasf + (size_t)h*16384;
    for (int idx = n; idx < 16384; idx += 128)
        sc[(idx >> 7)*129 + (idx & 127)] = mrow[idx] + brow[idx];
    __syncthreads();
    const float SC = 0.20412414523193154f;   // 24^-0.5
    float* myrow = sc + n*129;
    for (int m = 0; m < 128; m++) {
        float s = 0.f;
        const float* kr = ks + m*25;
        #pragma unroll
        for (int d = 0; d < 24; d++) s = fmaf(q[d], kr[d], s);
        myrow[m] = fmaf(s, SC, myrow[m]);
    }
    float mx = -1e30f;
    for (int m = 0; m < 128; m++) mx = fmaxf(mx, myrow[m]);
    float o[24] = {}; float ssum = 0.f;
    for (int m = 0; m < 128; m++) {
        float p = __expf(myrow[m] - mx);
        ssum += p;
        const float* vr = vs + m*25;
        #pragma unroll
        for (int d = 0; d < 24; d++) o[d] = fmaf(p, vr[d], o[d]);
    }
    float inv = 1.f / ssum;
    size_t ob = (size_t)(win*128 + n)*384 + 192 + h*24;
    #pragma unroll
    for (int d = 0; d < 24; d++) g_xout[ob + d] = o[d]*inv;
}

// ---------------- mutual attention: both halves in one block ----------------
__global__ void attn_mut(const float* __restrict__ mask) {
    extern __shared__ float sm[];
    int win = blockIdx.x >> 3, h = blockIdx.x & 7;
    int tid = threadIdx.x;
    int p = tid >> 6, r = tid & 63;
    float* ks = sm + p*1600;            // 64*25 each part
    float* vs = sm + 3200 + p*1600;
    float* sc = sm + 6400 + p*4160;     // 64*65 each part
    int kvtok = (p == 0) ? r : 64 + r;  // x1: kv = first half; x2: kv = second half
    int qtok  = (p == 0) ? 64 + r : r;  // x1: q = q2; x2: q = q1
    size_t kb = (size_t)(win*128 + kvtok)*576 + h*24;
    size_t qb = (size_t)(win*128 + qtok)*576 + h*24;
    float q[24];
    #pragma unroll
    for (int d = 0; d < 24; d++) {
        q[d]         = g_qkv[qb + d];
        ks[r*25 + d] = g_qkv[kb + 192 + d];
        vs[r*25 + d] = g_qkv[kb + 384 + d];
    }
    int mw = win % 192;
    const float* mrow = mask + (size_t)mw*16384;
    for (int idx = tid; idx < 4096; idx += 128) {
        int i = idx >> 6, j = idx & 63;
        float v = mrow[i*128 + j];
        sm[6400 + i*65 + j] = v;
        sm[6400 + 4160 + i*65 + j] = v;
    }
    __syncthreads();
    const float SC = 0.20412414523193154f;
    float* myrow = sc + r*65;
    for (int m = 0; m < 64; m++) {
        float s = 0.f;
        const float* kr = ks + m*25;
        #pragma unroll
        for (int d = 0; d < 24; d++) s = fmaf(q[d], kr[d], s);
        myrow[m] = fmaf(s, SC, myrow[m]);
    }
    float mx = -1e30f;
    for (int m = 0; m < 64; m++) mx = fmaxf(mx, myrow[m]);
    float o[24] = {}; float ssum = 0.f;
    for (int m = 0; m < 64; m++) {
        float pv = __expf(myrow[m] - mx);
        ssum += pv;
        const float* vr = vs + m*25;
        #pragma unroll
        for (int d = 0; d < 24; d++) o[d] = fmaf(pv, vr[d], o[d]);
    }
    float inv = 1.f / ssum;
    int orow = (p == 0) ? r : 64 + r;   // x1 -> rows 0..63, x2 -> rows 64..127
    size_t ob = (size_t)(win*128 + orow)*384 + h*24;
    #pragma unroll
    for (int d = 0; d < 24; d++) g_xout[ob + d] = o[d]*inv;
}

// --------- residual scatter (window->orig, unroll) + LN2 + gate top-2 -------
__global__ void resid_gate(const float* __restrict__ x,
                           const float* __restrict__ n2w, const float* __restrict__ n2b,
                           const float* __restrict__ gw,  const float* __restrict__ gb) {
    int t = blockIdx.x;          // original-order token
    int c = threadIdx.x;
    int b_ = t / 24576; int rrem = t % 24576;
    int d  = rrem / 4096; int r2 = rrem % 4096;
    int hh_ = r2 / 64; int ww_ = r2 % 64;
    int ds = d - 1; if (ds < 0) ds += 6;
    int hs = (hh_ + 60) & 63;
    int ws = (ww_ + 60) & 63;
    int dd = ds >> 1, wd = ds & 1;
    int hblk = hs >> 3, wh = hs & 7;
    int wblk = ws >> 3, wwp = ws & 7;
    int win = ((b_*3 + dd)*8 + hblk)*8 + wblk;
    int n = wd*64 + wh*8 + wwp;
    float v = x[(size_t)t*192 + c] + g_attnbuf[(size_t)(win*128 + n)*192 + c];
    g_xres[(size_t)t*192 + c] = v;

    __shared__ float s1[6], s2[6];
    __shared__ float sg[6][8];
    int wi = c >> 5, ln = c & 31;
    float a = warpsum(v), qq = warpsum(v*v);
    if (ln == 0) { s1[wi] = a; s2[wi] = qq; }
    __syncthreads();
    float S1 = 0.f, S2 = 0.f;
    #pragma unroll
    for (int i = 0; i < 6; i++) { S1 += s1[i]; S2 += s2[i]; }
    float mu  = S1 * (1.f/192.f);
    float var = S2 * (1.f/192.f) - mu*mu;
    float xn = (v - mu) * rsqrtf(var + 1e-5f) * n2w[c] + n2b[c];
    g_xn2[(size_t)t*192 + c] = xn;

    float g[8];
    #pragma unroll
    for (int j = 0; j < 8; j++) g[j] = xn * gw[c*8 + j];
    #pragma unroll
    for (int j = 0; j < 8; j++)
        #pragma unroll
        for (int o = 16; o; o >>= 1) g[j] += __shfl_down_sync(0xffffffffu, g[j], o);
    if (ln == 0) {
        #pragma unroll
        for (int j = 0; j < 8; j++) sg[wi][j] = g[j];
    }
    __syncthreads();
    if (c == 0) {
        float L[8];
        #pragma unroll
        for (int j = 0; j < 8; j++) {
            L[j] = gb[j];
            #pragma unroll
            for (int i = 0; i < 6; i++) L[j] += sg[i][j];
        }
        int e0 = 0;
        #pragma unroll
        for (int j = 1; j < 8; j++) if (L[j] > L[e0]) e0 = j;
        int e1 = (e0 == 0) ? 1 : 0;
        #pragma unroll
        for (int j = 0; j < 8; j++) if (j != e0 && L[j] > L[e1]) e1 = j;
        float w0 = 1.f / (1.f + __expf(L[e1] - L[e0]));
        float w1 = 1.f - w0;
        int p0 = atomicAdd(&g_cnt[e0], 1);
        g_gidx[e0*TTOK + p0] = t; g_gw[e0*TTOK + p0] = w0; g_grank[e0*TTOK + p0] = 0;
        int p1 = atomicAdd(&g_cnt[e1], 1);
        g_gidx[e1*TTOK + p1] = t; g_gw[e1*TTOK + p1] = w1; g_grank[e1*TTOK + p1] = 1;
    }
}

// ---------------- MoE: gathered per-expert fused GEMM-gelu-GEMM --------------
__global__ __launch_bounds__(256)
void moe(const float* __restrict__ W1, const float* __restrict__ b1,
         const float* __restrict__ W2, const float* __restrict__ b2) {
    int e = blockIdx.y;
    int cnt = g_cnt[e];
    int base = blockIdx.x * 64;
    if (base >= cnt) return;
    int rows = min(64, cnt - base);
    extern __shared__ float sm[];
    float* As = sm;                  // 64*196
    float* Hs = sm + 64*196;         // 64*388
    __shared__ int tok[64]; __shared__ float wgt[64]; __shared__ int rnk[64];
    int tid = threadIdx.x;
    if (tid < 64) {
        if (tid < rows) {
            tok[tid] = g_gidx[e*TTOK + base + tid];
            wgt[tid] = g_gw[e*TTOK + base + tid];
            rnk[tid] = g_grank[e*TTOK + base + tid];
        } else tok[tid] = -1;
    }
    __syncthreads();
    for (int idx = tid; idx < 64*48; idx += 256) {
        int rr = idx / 48; int c4 = (idx % 48)*4;
        float4 v = make_float4(0.f, 0.f, 0.f, 0.f);
        if (rr < rows) v = *reinterpret_cast<const float4*>(&g_xn2[(size_t)tok[rr]*192 + c4]);
        As[rr*196 + c4+0] = v.x; As[rr*196 + c4+1] = v.y;
        As[rr*196 + c4+2] = v.z; As[rr*196 + c4+3] = v.w;
    }
    __syncthreads();
    int tx = tid & 15, ty = tid >> 4;
    const float* W1e = W1 + (size_t)e*73728;
    const float* b1e = b1 + e*384;
    for (int jp = 0; jp < 6; jp++) {
        float acc[4][4] = {};
        int col = jp*64 + tx*4;
        for (int k = 0; k < 192; k++) {
            float4 bv = *reinterpret_cast<const float4*>(&W1e[(size_t)k*384 + col]);
            #pragma unroll
            for (int i = 0; i < 4; i++) {
                float a = As[(ty*4 + i)*196 + k];
                acc[i][0] = fmaf(a, bv.x, acc[i][0]);
                acc[i][1] = fmaf(a, bv.y, acc[i][1]);
                acc[i][2] = fmaf(a, bv.z, acc[i][2]);
                acc[i][3] = fmaf(a, bv.w, acc[i][3]);
            }
        }
        #pragma unroll
        for (int i = 0; i < 4; i++)
            #pragma unroll
            for (int j = 0; j < 4; j++) {
                float hv = acc[i][j] + b1e[col + j];
                hv = hv * normcdff(hv);        // exact gelu
                Hs[(ty*4 + i)*388 + col + j] = hv;
            }
    }
    __syncthreads();
    const float* W2e = W2 + (size_t)e*73728;
    const float* b2e = b2 + e*192;
    for (int jp = 0; jp < 3; jp++) {
        float acc[4][4] = {};
        int col = jp*64 + tx*4;
        for (int k = 0; k < 384; k++) {
            float4 bv = *reinterpret_cast<const float4*>(&W2e[(size_t)k*192 + col]);
            #pragma unroll
            for (int i = 0; i < 4; i++) {
                float a = Hs[(ty*4 + i)*388 + k];
                acc[i][0] = fmaf(a, bv.x, acc[i][0]);
                acc[i][1] = fmaf(a, bv.y, acc[i][1]);
                acc[i][2] = fmaf(a, bv.z, acc[i][2]);
                acc[i][3] = fmaf(a, bv.w, acc[i][3]);
            }
        }
        #pragma unroll
        for (int i = 0; i < 4; i++) {
            int rr = ty*4 + i;
            if (rr < rows) {
                float w = wgt[rr]; int tt = tok[rr];
                float* dst = (rnk[rr] == 0) ? g_contrib0 : g_contrib1;
                #pragma unroll
                for (int j = 0; j < 4; j++)
                    dst[(size_t)tt*192 + col + j] = w * (acc[i][j] + b2e[col + j]);
            }
        }
    }
}

// ---------------- finalize: out = xres + contrib0 + contrib1 ----------------
__global__ void finalize(float* __restrict__ out) {
    int i = blockIdx.x*blockDim.x + threadIdx.x;
    if (i < TTOK*48) {
        float4 a  = reinterpret_cast<const float4*>(g_xres)[i];
        float4 c0 = reinterpret_cast<const float4*>(g_contrib0)[i];
        float4 c1 = reinterpret_cast<const float4*>(g_contrib1)[i];
        reinterpret_cast<float4*>(out)[i] =
            make_float4(a.x + c0.x + c1.x, a.y + c0.y + c1.y,
                        a.z + c0.z + c1.z, a.w + c0.w + c1.w);
    }
}

// ---------------- host launcher ----------------------------------------------
extern "C" void kernel_launch(void* const* d_in, const int* in_sizes, int n_in,
                              void* d_out, int out_size) {
    const float* x    = (const float*)d_in[0];
    const float* mask = (const float*)d_in[1];
    const float* n1w  = (const float*)d_in[2];
    const float* n1b  = (const float*)d_in[3];
    const float* qsw  = (const float*)d_in[4];
    const float* qsb  = (const float*)d_in[5];
    const float* qmw  = (const float*)d_in[6];
    const float* qmb  = (const float*)d_in[7];
    const float* rpb  = (const float*)d_in[8];
    const float* pw   = (const float*)d_in[9];
    const float* pb   = (const float*)d_in[10];
    const float* n2w  = (const float*)d_in[11];
    const float* n2b  = (const float*)d_in[12];
    const float* gw   = (const float*)d_in[13];
    const float* gb   = (const float*)d_in[14];
    const float* W1   = (const float*)d_in[15];
    const float* b1   = (const float*)d_in[16];
    const float* W2   = (const float*)d_in[17];
    const float* b2   = (const float*)d_in[18];
    float* out = (float*)d_out;

    cudaFuncSetAttribute(attn_self, cudaFuncAttributeMaxDynamicSharedMemorySize, 94208);
    cudaFuncSetAttribute(attn_mut,  cudaFuncAttributeMaxDynamicSharedMemorySize, 61440);
    cudaFuncSetAttribute(moe,       cudaFuncAttributeMaxDynamicSharedMemorySize, 153600);

    float *p_xw, *p_qkv, *p_xout, *p_attn;
    cudaGetSymbolAddress((void**)&p_xw,   g_xw);
    cudaGetSymbolAddress((void**)&p_qkv,  g_qkv);
    cudaGetSymbolAddress((void**)&p_xout, g_xout);
    cudaGetSymbolAddress((void**)&p_attn, g_attnbuf);

    k_pos<<<1, 192>>>();
    k_bias<<<128, 128>>>(rpb);
    ln_partition<<<TTOK, 192>>>(x, n1w, n1b);
    gemm64<<<dim3(768, 9), 256>>>(p_xw, qsw, qsb, p_qkv, 192, 576, 0);
    attn_self<<<NWIN*8, 128, 91648>>>(mask);
    gemm64<<<dim3(768, 9), 256>>>(p_xw, qmw, qmb, p_qkv, 192, 576, 1);
    attn_mut<<<NWIN*8, 128, 58880>>>(mask);
    gemm64<<<dim3(768, 3), 256>>>(p_xout, pw, pb, p_attn, 384, 192, 0);
    resid_gate<<<TTOK, 192>>>(x, n2w, n2b, gw, gb);
    moe<<<dim3(768, 8), 256, 149504>>>(W1, b1, W2, b2);
    finalize<<<9216, 256>>>(out);
}

// round 3
// speedup vs baseline: 3.6808x; 3.6808x over previous
#include <cuda_runtime.h>
#include <cuda_bf16.h>
#include <math.h>
#include <cstdint>

#define TTOK 49152      // total tokens = 2*6*64*64
#define NWIN 384

// ---------------- scratch (device globals; no allocations allowed) ----------
__device__ float g_qkv[TTOK*576];       // qkv fp32 (reused self & mutual)
__device__ float g_attnbuf[TTOK*192];   // proj output (window order)
__device__ float g_xres[TTOK*192];      // x + attn residual (original order)
__device__ float g_pos[64*192];
__device__ float g_biasf[8*128*128];
__device__ int   g_cnt[8];
__device__ int   g_gidx[8*TTOK];
__device__ float g_gw[8*TTOK];
__device__ int   g_grank[8*TTOK];
__device__ float g_contrib0[TTOK*192];
__device__ float g_contrib1[TTOK*192];
// bf16 activation buffers for tensor-core GEMMs
__device__ __nv_bfloat16 g_xw_bf[TTOK*192];
__device__ __nv_bfloat16 g_xm_bf[TTOK*192];
__device__ __nv_bfloat16 g_xout_bf[TTOK*384];
__device__ __nv_bfloat16 g_xn2_bf[TTOK*192];
__device__ __nv_bfloat16 g_hbuf[(size_t)8*TTOK*384];
// transposed bf16 weights [N][K]
__device__ __nv_bfloat16 g_wt_qs[576*192];
__device__ __nv_bfloat16 g_wt_qm[576*192];
__device__ __nv_bfloat16 g_wt_p [192*384];
__device__ __nv_bfloat16 g_wt_w1[8*384*192];
__device__ __nv_bfloat16 g_wt_w2[8*192*384];

// ---------------- warp helpers ------------------------------------------------
__device__ __forceinline__ float warpsum(float v) {
    #pragma unroll
    for (int o = 16; o; o >>= 1) v += __shfl_down_sync(0xffffffffu, v, o);
    return v;
}
__device__ __forceinline__ uint32_t smem_u32(const void* p) {
    uint32_t a;
    asm("{ .reg .u64 t; cvta.to.shared.u64 t, %1; cvt.u32.u64 %0, t; }" : "=r"(a) : "l"(p));
    return a;
}
__device__ __forceinline__ void ldsm_x4(uint32_t& r0, uint32_t& r1, uint32_t& r2,
                                        uint32_t& r3, uint32_t addr) {
    asm volatile("ldmatrix.sync.aligned.m8n8.x4.shared.b16 {%0,%1,%2,%3}, [%4];"
                 : "=r"(r0), "=r"(r1), "=r"(r2), "=r"(r3) : "r"(addr));
}
__device__ __forceinline__ void mma16816(float* c, uint32_t a0, uint32_t a1,
                                         uint32_t a2, uint32_t a3,
                                         uint32_t b0, uint32_t b1) {
    asm volatile("mma.sync.aligned.m16n8k16.row.col.f32.bf16.bf16.f32 "
        "{%0,%1,%2,%3}, {%4,%5,%6,%7}, {%8,%9}, {%0,%1,%2,%3};"
        : "+f"(c[0]), "+f"(c[1]), "+f"(c[2]), "+f"(c[3])
        : "r"(a0), "r"(a1), "r"(a2), "r"(a3), "r"(b0), "r"(b1));
}
#define SMEM_SWZ(o) ((o) ^ (((o) >> 3) & 0x70))

// ================= bf16 HMMA GEMM: block tile 128 x 64 ======================
// MODE 0: C fp32 = A_bf @ Bt_bf^T + bias          (A rows = token index)
// MODE 1: MoE FC1: gather rows via g_gidx, gelu, bf16 -> g_hbuf
// MODE 2: MoE FC2: rows = H slots, weighted scatter -> g_contrib{0,1}
template<int MODE>
__global__ __launch_bounds__(256) void gemm_mma(
        const __nv_bfloat16* __restrict__ A,
        const __nv_bfloat16* __restrict__ Bt,
        const float* __restrict__ bias,
        float* __restrict__ Cf, int K, int ldC) {
    __shared__ __align__(1024) uint8_t sA[16384];   // 128 x 64 bf16, SW128
    __shared__ __align__(1024) uint8_t sB[8192];    // 64 x 64 bf16, SW128
    __shared__ int s_tok[128]; __shared__ float s_wgt[128]; __shared__ int s_rnk[128];

    int tid = threadIdx.x, wid = tid >> 5, lane = tid & 31;
    int wm = wid >> 1, wn = wid & 1;           // warp grid 4 x 2
    int row0 = blockIdx.x * 128, col0 = blockIdx.y * 64;
    int e = blockIdx.z;
    int cnt = TTOK;
    if (MODE != 0) { cnt = g_cnt[e]; if (row0 >= cnt) return; }
    const __nv_bfloat16* Bte = Bt + (size_t)e * ldC * K;
    const float* be = bias + (size_t)e * ldC;
    const __nv_bfloat16* Ae = (MODE == 2) ? (A + (size_t)e * TTOK * K) : A;

    if (MODE != 0 && tid < 128) {
        int slot = row0 + tid;
        if (slot < cnt) {
            s_tok[tid] = g_gidx[e*TTOK + slot];
            s_wgt[tid] = g_gw[e*TTOK + slot];
            s_rnk[tid] = g_grank[e*TTOK + slot];
        } else s_tok[tid] = -1;
    }
    if (MODE != 0) __syncthreads();

    uint32_t aBase = smem_u32(sA), bBase = smem_u32(sB);
    float c[2][4][4] = {};
    int srow = tid >> 3, c16 = tid & 7;        // staging coords

    for (int kc = 0; kc < K; kc += 64) {
        // stage A: 128 rows x 64 bf16
        #pragma unroll
        for (int i = 0; i < 4; i++) {
            int r = i*32 + srow;
            uint4 v = make_uint4(0,0,0,0);
            if (MODE == 1) {
                int tk = s_tok[r];
                if (tk >= 0) v = *reinterpret_cast<const uint4*>(Ae + (size_t)tk*K + kc + c16*8);
            } else if (MODE == 2) {
                if (row0 + r < cnt) v = *reinterpret_cast<const uint4*>(Ae + (size_t)(row0+r)*K + kc + c16*8);
            } else {
                v = *reinterpret_cast<const uint4*>(Ae + (size_t)(row0+r)*K + kc + c16*8);
            }
            *reinterpret_cast<uint4*>(sA + SMEM_SWZ((uint32_t)(r*128 + c16*16))) = v;
        }
        // stage B: 64 rows x 64 bf16
        #pragma unroll
        for (int i = 0; i < 2; i++) {
            int r = i*32 + srow;
            uint4 v = *reinterpret_cast<const uint4*>(Bte + (size_t)(col0+r)*K + kc + c16*8);
            *reinterpret_cast<uint4*>(sB + SMEM_SWZ((uint32_t)(r*128 + c16*16))) = v;
        }
        __syncthreads();
        int g = lane >> 3, l7 = lane & 7;
        #pragma unroll
        for (int ks = 0; ks < 4; ks++) {
            uint32_t a[2][4];
            #pragma unroll
            for (int mi = 0; mi < 2; mi++) {
                int r = wm*32 + mi*16 + ((g & 1) << 3) + l7;
                int kb = ks*32 + ((g >> 1) << 4);
                ldsm_x4(a[mi][0], a[mi][1], a[mi][2], a[mi][3],
                        aBase + SMEM_SWZ((uint32_t)(r*128 + kb)));
            }
            uint32_t b[4][2];
            #pragma unroll
            for (int np = 0; np < 2; np++) {
                int r = wn*32 + np*16 + ((g >> 1) << 3) + l7;
                int kb = ks*32 + ((g & 1) << 4);
                uint32_t r0, r1, r2, r3;
                ldsm_x4(r0, r1, r2, r3, bBase + SMEM_SWZ((uint32_t)(r*128 + kb)));
                b[np*2][0] = r0;   b[np*2][1] = r1;
                b[np*2+1][0] = r2; b[np*2+1][1] = r3;
            }
            #pragma unroll
            for (int mi = 0; mi < 2; mi++)
                #pragma unroll
                for (int nj = 0; nj < 4; nj++)
                    mma16816(c[mi][nj], a[mi][0], a[mi][1], a[mi][2], a[mi][3],
                             b[nj][0], b[nj][1]);
        }
        __syncthreads();
    }

    // ---------------- epilogue -------------------------------------------------
    int qr = lane >> 2, qc = (lane & 3) * 2;
    #pragma unroll
    for (int mi = 0; mi < 2; mi++) {
        #pragma unroll
        for (int h = 0; h < 2; h++) {
            int lr = wm*32 + mi*16 + h*8 + qr;       // local row 0..127
            #pragma unroll
            for (int nj = 0; nj < 4; nj++) {
                int col = col0 + wn*32 + nj*8 + qc;
                float v0 = c[mi][nj][2*h + 0];
                float v1 = c[mi][nj][2*h + 1];
                if (MODE == 0) {
                    size_t crow = (size_t)(row0 + lr)*ldC + col;
                    float2 o = make_float2(v0 + be[col], v1 + be[col+1]);
                    *reinterpret_cast<float2*>(Cf + crow) = o;
                } else if (MODE == 1) {
                    if (s_tok[lr] >= 0) {
                        float h0 = v0 + be[col], h1 = v1 + be[col+1];
                        h0 = h0 * normcdff(h0);
                        h1 = h1 * normcdff(h1);
                        __nv_bfloat162 p;
                        p.x = __float2bfloat16_rn(h0); p.y = __float2bfloat16_rn(h1);
                        *reinterpret_cast<__nv_bfloat162*>(
                            g_hbuf + ((size_t)e*TTOK + row0 + lr)*384 + col) = p;
                    }
                } else {
                    int tk = s_tok[lr];
                    if (tk >= 0) {
                        float w = s_wgt[lr];
                        float* dst = (s_rnk[lr] == 0) ? g_contrib0 : g_contrib1;
                        float2 o = make_float2(w*(v0 + be[col]), w*(v1 + be[col+1]));
                        *reinterpret_cast<float2*>(dst + (size_t)tk*192 + col) = o;
                    }
                }
            }
        }
    }
}

// ---------------- prep: sine positional encoding + zero counters ------------
__global__ void k_pos() {
    int c = threadIdx.x;
    if (c < 8) g_cnt[c] = 0;
    const float TWO_PI = 6.283185307179586f;
    const float denom = 8.0f + 1e-6f;
    int f = (c < 96) ? c : c - 96;
    float expo = (float)(f & ~1) / 96.0f;
    float dt = powf(10000.0f, expo);
    for (int n = 0; n < 64; n++) {
        int i = n >> 3, j = n & 7;
        float base = (c < 96) ? (float)(i + 1) : (float)(j + 1);
        float v = base / denom * TWO_PI / dt;
        g_pos[n*192 + c] = (f & 1) ? cosf(v) : sinf(v);
    }
}

// ---------------- prep: rel-pos bias table -----------------------------------
__global__ void k_bias(const float* __restrict__ rpb) {
    int n = blockIdx.x, m = threadIdx.x;
    int dn = n >> 6, hn = (n >> 3) & 7, wn = n & 7;
    int dm = m >> 6, hm = (m >> 3) & 7, wm = m & 7;
    int rp = (dn - dm + 1)*225 + (hn - hm + 7)*15 + (wn - wm + 7);
    #pragma unroll
    for (int h = 0; h < 8; h++)
        g_biasf[h*16384 + n*128 + m] = rpb[rp*8 + h];
}

// ---------------- prep: weight transposes -> bf16 [N][K] ---------------------
__global__ void k_transpose(const float* __restrict__ qs, const float* __restrict__ qm,
                            const float* __restrict__ pw, const float* __restrict__ W1,
                            const float* __restrict__ W2) {
    int i = blockIdx.x*blockDim.x + threadIdx.x;
    const int S1 = 576*192, S2 = 2*S1, S3 = S2 + 192*384;
    const int S4 = S3 + 8*384*192, S5 = S4 + 8*192*384;
    if (i < S1) {
        int n = i/192, k = i%192;
        g_wt_qs[i] = __float2bfloat16_rn(qs[k*576 + n]);
    } else if (i < S2) {
        int j = i - S1; int n = j/192, k = j%192;
        g_wt_qm[j] = __float2bfloat16_rn(qm[k*576 + n]);
    } else if (i < S3) {
        int j = i - S2; int n = j/384, k = j%384;
        g_wt_p[j] = __float2bfloat16_rn(pw[k*192 + n]);
    } else if (i < S4) {
        int j = i - S3; int e = j/73728, rr = j%73728;
        int n = rr/192, k = rr%192;
        g_wt_w1[j] = __float2bfloat16_rn(W1[e*73728 + k*384 + n]);
    } else if (i < S5) {
        int j = i - S4; int e = j/73728, rr = j%73728;
        int n = rr/384, k = rr%384;
        g_wt_w2[j] = __float2bfloat16_rn(W2[e*73728 + k*192 + n]);
    }
}

// ---------------- LN1 + roll + window partition -> bf16 ----------------------
__global__ void ln_partition(const float* __restrict__ x,
                             const float* __restrict__ w1,
                             const float* __restrict__ b1) {
    int t = blockIdx.x, c = threadIdx.x;
    int win = t >> 7, n = t & 127;
    int b_  = win / 192; int rem = win % 192;
    int dd  = rem / 64;  int rem2 = rem % 64;
    int hh  = rem2 >> 3; int ww = rem2 & 7;
    int wd  = n >> 6, wh = (n >> 3) & 7, wwp = n & 7;
    int ds = dd*2 + wd, hs = hh*8 + wh, ws = ww*8 + wwp;
    int d = ds + 1; if (d >= 6) d -= 6;
    int h = (hs + 4) & 63;
    int w = (ws + 4) & 63;
    size_t src = (size_t)(((b_*6 + d)*64 + h)*64 + w)*192 + c;
    float v = x[src];
    __shared__ float s1[6], s2[6];
    int wi = c >> 5, ln = c & 31;
    float a = warpsum(v), q = warpsum(v*v);
    if (ln == 0) { s1[wi] = a; s2[wi] = q; }
    __syncthreads();
    float S1 = 0.f, S2 = 0.f;
    #pragma unroll
    for (int i = 0; i < 6; i++) { S1 += s1[i]; S2 += s2[i]; }
    float mu  = S1 * (1.f/192.f);
    float var = S2 * (1.f/192.f) - mu*mu;
    float y = (v - mu) * rsqrtf(var + 1e-5f) * w1[c] + b1[c];
    g_xw_bf[(size_t)t*192 + c] = __float2bfloat16_rn(y);
    g_xm_bf[(size_t)t*192 + c] = __float2bfloat16_rn(y + g_pos[(n & 63)*192 + c]);
}

// ---------------- self attention ---------------------------------------------
__global__ void attn_self(const float* __restrict__ mask) {
    extern __shared__ float sm[];
    float* ks = sm;
    float* vs = sm + 3200;
    float* sc = sm + 6400;
    int win = blockIdx.x >> 3, h = blockIdx.x & 7;
    int n = threadIdx.x;
    size_t base = (size_t)(win*128 + n)*576 + h*24;
    float q[24];
    #pragma unroll
    for (int d = 0; d < 24; d++) {
        q[d]          = g_qkv[base + d];
        ks[n*25 + d]  = g_qkv[base + 192 + d];
        vs[n*25 + d]  = g_qkv[base + 384 + d];
    }
    int mw = win % 192;
    const float* mrow = mask + (size_t)mw*16384;
    const float* brow = g_biasf + (size_t)h*16384;
    for (int idx = n; idx < 16384; idx += 128)
        sc[(idx >> 7)*129 + (idx & 127)] = mrow[idx] + brow[idx];
    __syncthreads();
    const float SC = 0.20412414523193154f;
    float* myrow = sc + n*129;
    for (int m = 0; m < 128; m++) {
        float s = 0.f;
        const float* kr = ks + m*25;
        #pragma unroll
        for (int d = 0; d < 24; d++) s = fmaf(q[d], kr[d], s);
        myrow[m] = fmaf(s, SC, myrow[m]);
    }
    float mx = -1e30f;
    for (int m = 0; m < 128; m++) mx = fmaxf(mx, myrow[m]);
    float o[24] = {}; float ssum = 0.f;
    for (int m = 0; m < 128; m++) {
        float p = __expf(myrow[m] - mx);
        ssum += p;
        const float* vr = vs + m*25;
        #pragma unroll
        for (int d = 0; d < 24; d++) o[d] = fmaf(p, vr[d], o[d]);
    }
    float inv = 1.f / ssum;
    size_t ob = (size_t)(win*128 + n)*384 + 192 + h*24;
    #pragma unroll
    for (int d = 0; d < 24; d++) g_xout_bf[ob + d] = __float2bfloat16_rn(o[d]*inv);
}

// ---------------- mutual attention -------------------------------------------
__global__ void attn_mut(const float* __restrict__ mask) {
    extern __shared__ float sm[];
    int win = blockIdx.x >> 3, h = blockIdx.x & 7;
    int tid = threadIdx.x;
    int p = tid >> 6, r = tid & 63;
    float* ks = sm + p*1600;
    float* vs = sm + 3200 + p*1600;
    float* sc = sm + 6400 + p*4160;
    int kvtok = (p == 0) ? r : 64 + r;
    int qtok  = (p == 0) ? 64 + r : r;
    size_t kb = (size_t)(win*128 + kvtok)*576 + h*24;
    size_t qb = (size_t)(win*128 + qtok)*576 + h*24;
    float q[24];
    #pragma unroll
    for (int d = 0; d < 24; d++) {
        q[d]         = g_qkv[qb + d];
        ks[r*25 + d] = g_qkv[kb + 192 + d];
        vs[r*25 + d] = g_qkv[kb + 384 + d];
    }
    int mw = win % 192;
    const float* mrow = mask + (size_t)mw*16384;
    for (int idx = tid; idx < 4096; idx += 128) {
        int i = idx >> 6, j = idx & 63;
        float v = mrow[i*128 + j];
        sm[6400 + i*65 + j] = v;
        sm[6400 + 4160 + i*65 + j] = v;
    }
    __syncthreads();
    const float SC = 0.20412414523193154f;
    float* myrow = sc + r*65;
    for (int m = 0; m < 64; m++) {
        float s = 0.f;
        const float* kr = ks + m*25;
        #pragma unroll
        for (int d = 0; d < 24; d++) s = fmaf(q[d], kr[d], s);
        myrow[m] = fmaf(s, SC, myrow[m]);
    }
    float mx = -1e30f;
    for (int m = 0; m < 64; m++) mx = fmaxf(mx, myrow[m]);
    float o[24] = {}; float ssum = 0.f;
    for (int m = 0; m < 64; m++) {
        float pv = __expf(myrow[m] - mx);
        ssum += pv;
        const float* vr = vs + m*25;
        #pragma unroll
        for (int d = 0; d < 24; d++) o[d] = fmaf(pv, vr[d], o[d]);
    }
    float inv = 1.f / ssum;
    int orow = (p == 0) ? r : 64 + r;
    size_t ob = (size_t)(win*128 + orow)*384 + h*24;
    #pragma unroll
    for (int d = 0; d < 24; d++) g_xout_bf[ob + d] = __float2bfloat16_rn(o[d]*inv);
}

// --------- residual scatter + LN2 + gate top-2 -------------------------------
__global__ void resid_gate(const float* __restrict__ x,
                           const float* __restrict__ n2w, const float* __restrict__ n2b,
                           const float* __restrict__ gw,  const float* __restrict__ gb) {
    int t = blockIdx.x, c = threadIdx.x;
    int b_ = t / 24576; int rrem = t % 24576;
    int d  = rrem / 4096; int r2 = rrem % 4096;
    int hh_ = r2 / 64; int ww_ = r2 % 64;
    int ds = d - 1; if (ds < 0) ds += 6;
    int hs = (hh_ + 60) & 63;
    int ws = (ww_ + 60) & 63;
    int dd = ds >> 1, wd = ds & 1;
    int hblk = hs >> 3, wh = hs & 7;
    int wblk = ws >> 3, wwp = ws & 7;
    int win = ((b_*3 + dd)*8 + hblk)*8 + wblk;
    int n = wd*64 + wh*8 + wwp;
    float v = x[(size_t)t*192 + c] + g_attnbuf[(size_t)(win*128 + n)*192 + c];
    g_xres[(size_t)t*192 + c] = v;
    __shared__ float s1[6], s2[6];
    __shared__ float sg[6][8];
    int wi = c >> 5, ln = c & 31;
    float a = warpsum(v), qq = warpsum(v*v);
    if (ln == 0) { s1[wi] = a; s2[wi] = qq; }
    __syncthreads();
    float S1 = 0.f, S2 = 0.f;
    #pragma unroll
    for (int i = 0; i < 6; i++) { S1 += s1[i]; S2 += s2[i]; }
    float mu  = S1 * (1.f/192.f);
    float var = S2 * (1.f/192.f) - mu*mu;
    float xn = (v - mu) * rsqrtf(var + 1e-5f) * n2w[c] + n2b[c];
    g_xn2_bf[(size_t)t*192 + c] = __float2bfloat16_rn(xn);
    float g[8];
    #pragma unroll
    for (int j = 0; j < 8; j++) g[j] = xn * gw[c*8 + j];
    #pragma unroll
    for (int j = 0; j < 8; j++)
        #pragma unroll
        for (int o = 16; o; o >>= 1) g[j] += __shfl_down_sync(0xffffffffu, g[j], o);
    if (ln == 0) {
        #pragma unroll
        for (int j = 0; j < 8; j++) sg[wi][j] = g[j];
    }
    __syncthreads();
    if (c == 0) {
        float L[8];
        #pragma unroll
        for (int j = 0; j < 8; j++) {
            L[j] = gb[j];
            #pragma unroll
            for (int i = 0; i < 6; i++) L[j] += sg[i][j];
        }
        int e0 = 0;
        #pragma unroll
        for (int j = 1; j < 8; j++) if (L[j] > L[e0]) e0 = j;
        int e1 = (e0 == 0) ? 1 : 0;
        #pragma unroll
        for (int j = 0; j < 8; j++) if (j != e0 && L[j] > L[e1]) e1 = j;
        float w0 = 1.f / (1.f + __expf(L[e1] - L[e0]));
        float w1 = 1.f - w0;
        int p0 = atomicAdd(&g_cnt[e0], 1);
        g_gidx[e0*TTOK + p0] = t; g_gw[e0*TTOK + p0] = w0; g_grank[e0*TTOK + p0] = 0;
        int p1 = atomicAdd(&g_cnt[e1], 1);
        g_gidx[e1*TTOK + p1] = t; g_gw[e1*TTOK + p1] = w1; g_grank[e1*TTOK + p1] = 1;
    }
}

// ---------------- finalize ----------------------------------------------------
__global__ void finalize(float* __restrict__ out) {
    int i = blockIdx.x*blockDim.x + threadIdx.x;
    if (i < TTOK*48) {
        float4 a  = reinterpret_cast<const float4*>(g_xres)[i];
        float4 c0 = reinterpret_cast<const float4*>(g_contrib0)[i];
        float4 c1 = reinterpret_cast<const float4*>(g_contrib1)[i];
        reinterpret_cast<float4*>(out)[i] =
            make_float4(a.x + c0.x + c1.x, a.y + c0.y + c1.y,
                        a.z + c0.z + c1.z, a.w + c0.w + c1.w);
    }
}

// ---------------- host launcher -----------------------------------------------
extern "C" void kernel_launch(void* const* d_in, const int* in_sizes, int n_in,
                              void* d_out, int out_size) {
    const float* x    = (const float*)d_in[0];
    const float* mask = (const float*)d_in[1];
    const float* n1w  = (const float*)d_in[2];
    const float* n1b  = (const float*)d_in[3];
    const float* qsw  = (const float*)d_in[4];
    const float* qsb  = (const float*)d_in[5];
    const float* qmw  = (const float*)d_in[6];
    const float* qmb  = (const float*)d_in[7];
    const float* rpb  = (const float*)d_in[8];
    const float* pw   = (const float*)d_in[9];
    const float* pb   = (const float*)d_in[10];
    const float* n2w  = (const float*)d_in[11];
    const float* n2b  = (const float*)d_in[12];
    const float* gw   = (const float*)d_in[13];
    const float* gb   = (const float*)d_in[14];
    const float* W1   = (const float*)d_in[15];
    const float* b1   = (const float*)d_in[16];
    const float* W2   = (const float*)d_in[17];
    const float* b2   = (const float*)d_in[18];
    float* out = (float*)d_out;

    cudaFuncSetAttribute(attn_self, cudaFuncAttributeMaxDynamicSharedMemorySize, 94208);
    cudaFuncSetAttribute(attn_mut,  cudaFuncAttributeMaxDynamicSharedMemorySize, 61440);

    void *p_xw, *p_xm, *p_xout, *p_xn2, *p_h, *p_qkv, *p_attn;
    void *p_wqs, *p_wqm, *p_wp, *p_w1, *p_w2;
    cudaGetSymbolAddress(&p_xw,  g_xw_bf);
    cudaGetSymbolAddress(&p_xm,  g_xm_bf);
    cudaGetSymbolAddress(&p_xout,g_xout_bf);
    cudaGetSymbolAddress(&p_xn2, g_xn2_bf);
    cudaGetSymbolAddress(&p_h,   g_hbuf);
    cudaGetSymbolAddress(&p_qkv, g_qkv);
    cudaGetSymbolAddress(&p_attn,g_attnbuf);
    cudaGetSymbolAddress(&p_wqs, g_wt_qs);
    cudaGetSymbolAddress(&p_wqm, g_wt_qm);
    cudaGetSymbolAddress(&p_wp,  g_wt_p);
    cudaGetSymbolAddress(&p_w1,  g_wt_w1);
    cudaGetSymbolAddress(&p_w2,  g_wt_w2);

    k_pos<<<1, 192>>>();
    k_bias<<<128, 128>>>(rpb);
    k_transpose<<<5760, 256>>>(qsw, qmw, pw, W1, W2);
    ln_partition<<<TTOK, 192>>>(x, n1w, n1b);
    gemm_mma<0><<<dim3(384, 9), 256>>>((const __nv_bfloat16*)p_xw,
        (const __nv_bfloat16*)p_wqs, qsb, (float*)p_qkv, 192, 576);
    attn_self<<<NWIN*8, 128, 91648>>>(mask);
    gemm_mma<0><<<dim3(384, 9), 256>>>((const __nv_bfloat16*)p_xm,
        (const __nv_bfloat16*)p_wqm, qmb, (float*)p_qkv, 192, 576);
    attn_mut<<<NWIN*8, 128, 58880>>>(mask);
    gemm_mma<0><<<dim3(384, 3), 256>>>((const __nv_bfloat16*)p_xout,
        (const __nv_bfloat16*)p_wp, pb, (float*)p_attn, 384, 192);
    resid_gate<<<TTOK, 192>>>(x, n2w, n2b, gw, gb);
    gemm_mma<1><<<dim3(384, 6, 8), 256>>>((const __nv_bfloat16*)p_xn2,
        (const __nv_bfloat16*)p_w1, b1, nullptr, 192, 384);
    gemm_mma<2><<<dim3(384, 3, 8), 256>>>((const __nv_bfloat16*)p_h,
        (const __nv_bfloat16*)p_w2, b2, nullptr, 384, 192);
    finalize<<<9216, 256>>>(out);
}

// round 4
// speedup vs baseline: 6.2311x; 1.6929x over previous
#include <cuda_runtime.h>
#include <cuda_bf16.h>
#include <math.h>
#include <cstdint>

#define TTOK 49152      // total tokens = 2*6*64*64
#define NWIN 384

// ---------------- scratch (device globals; no allocations allowed) ----------
__device__ float g_qkv[TTOK*576];       // qkv fp32 (reused self & mutual)
__device__ float g_attnbuf[TTOK*192];   // proj output (window order)
__device__ float g_xres[TTOK*192];      // x + attn residual (original order)
__device__ float g_pos[64*192];
__device__ float g_bm[192*8*128*128];   // combined mask+bias, [mw][h][m][n]
__device__ int   g_cnt[8];
__device__ int   g_gidx[8*TTOK];
__device__ float g_gw[8*TTOK];
__device__ int   g_grank[8*TTOK];
__device__ float g_contrib0[TTOK*192];
__device__ float g_contrib1[TTOK*192];
// bf16 activation buffers for tensor-core GEMMs
__device__ __nv_bfloat16 g_xw_bf[TTOK*192];
__device__ __nv_bfloat16 g_xm_bf[TTOK*192];
__device__ __nv_bfloat16 g_xout_bf[TTOK*384];
__device__ __nv_bfloat16 g_xn2_bf[TTOK*192];
__device__ __nv_bfloat16 g_hbuf[(size_t)8*TTOK*384];
// transposed bf16 weights [N][K]
__device__ __nv_bfloat16 g_wt_qs[576*192];
__device__ __nv_bfloat16 g_wt_qm[576*192];
__device__ __nv_bfloat16 g_wt_p [192*384];
__device__ __nv_bfloat16 g_wt_w1[8*384*192];
__device__ __nv_bfloat16 g_wt_w2[8*192*384];

// ---------------- helpers ------------------------------------------------
__device__ __forceinline__ float warpsum_all(float v) {
    #pragma unroll
    for (int o = 16; o; o >>= 1) v += __shfl_xor_sync(0xffffffffu, v, o);
    return v;
}
__device__ __forceinline__ uint32_t smem_u32(const void* p) {
    uint32_t a;
    asm("{ .reg .u64 t; cvta.to.shared.u64 t, %1; cvt.u32.u64 %0, t; }" : "=r"(a) : "l"(p));
    return a;
}
__device__ __forceinline__ void ldsm_x4(uint32_t& r0, uint32_t& r1, uint32_t& r2,
                                        uint32_t& r3, uint32_t addr) {
    asm volatile("ldmatrix.sync.aligned.m8n8.x4.shared.b16 {%0,%1,%2,%3}, [%4];"
                 : "=r"(r0), "=r"(r1), "=r"(r2), "=r"(r3) : "r"(addr));
}
__device__ __forceinline__ void mma16816(float* c, uint32_t a0, uint32_t a1,
                                         uint32_t a2, uint32_t a3,
                                         uint32_t b0, uint32_t b1) {
    asm volatile("mma.sync.aligned.m16n8k16.row.col.f32.bf16.bf16.f32 "
        "{%0,%1,%2,%3}, {%4,%5,%6,%7}, {%8,%9}, {%0,%1,%2,%3};"
        : "+f"(c[0]), "+f"(c[1]), "+f"(c[2]), "+f"(c[3])
        : "r"(a0), "r"(a1), "r"(a2), "r"(a3), "r"(b0), "r"(b1));
}
__device__ __forceinline__ void cp16(uint32_t dst, const void* src, bool v) {
    asm volatile("cp.async.cg.shared.global [%0], [%1], 16, %2;"
                 :: "r"(dst), "l"(src), "r"(v ? 16u : 0u));
}
#define CP_COMMIT() asm volatile("cp.async.commit_group;")
#define CP_WAIT1()  asm volatile("cp.async.wait_group 1;")
#define CP_WAIT0()  asm volatile("cp.async.wait_group 0;")
#define SMEM_SWZ(o) ((o) ^ (((o) >> 3) & 0x70))

// ================= bf16 HMMA GEMM: block tile 128 x 64, cp.async 2-stage ====
// MODE 0: C fp32 = A_bf @ Bt_bf^T + bias
// MODE 1: MoE FC1: gather rows via g_gidx, gelu, bf16 -> g_hbuf
// MODE 2: MoE FC2: rows = H slots, weighted scatter -> g_contrib{0,1}
template<int MODE>
__global__ __launch_bounds__(256) void gemm_mma(
        const __nv_bfloat16* __restrict__ A,
        const __nv_bfloat16* __restrict__ Bt,
        const float* __restrict__ bias,
        float* __restrict__ Cf, int K, int ldC) {
    extern __shared__ uint8_t dyn_raw[];
    __shared__ int s_tok[128]; __shared__ float s_wgt[128]; __shared__ int s_rnk[128];

    int tid = threadIdx.x, wid = tid >> 5, lane = tid & 31;
    int wm = wid >> 1, wn = wid & 1;           // warp grid 4 x 2
    int row0 = blockIdx.x * 128, col0 = blockIdx.y * 64;
    int e = blockIdx.z;
    int cnt = TTOK;
    if (MODE != 0) { cnt = g_cnt[e]; if (row0 >= cnt) return; }
    const __nv_bfloat16* Bte = Bt + (size_t)e * ldC * K;
    const float* be = bias + (size_t)e * ldC;
    const __nv_bfloat16* Ae = (MODE == 2) ? (A + (size_t)e * TTOK * K) : A;

    if (MODE != 0 && tid < 128) {
        int slot = row0 + tid;
        if (slot < cnt) {
            s_tok[tid] = g_gidx[e*TTOK + slot];
            s_wgt[tid] = g_gw[e*TTOK + slot];
            s_rnk[tid] = g_grank[e*TTOK + slot];
        } else s_tok[tid] = -1;
    }
    if (MODE != 0) __syncthreads();

    uint32_t aBase = (smem_u32(dyn_raw) + 1023u) & ~1023u;
    uint32_t bBase = aBase + 32768;

    int srow = tid >> 3, c16 = tid & 7;        // staging coords
    const __nv_bfloat16* arp[4]; bool av[4]; uint32_t aOff[4];
    #pragma unroll
    for (int i = 0; i < 4; i++) {
        int r = i*32 + srow;
        aOff[i] = SMEM_SWZ((uint32_t)(r*128 + c16*16));
        if (MODE == 1) {
            int tk = s_tok[r];
            av[i] = (tk >= 0);
            arp[i] = Ae + (size_t)(av[i] ? tk : 0)*K + c16*8;
        } else if (MODE == 2) {
            av[i] = (row0 + r < cnt);
            arp[i] = Ae + (size_t)(av[i] ? (row0 + r) : 0)*K + c16*8;
        } else {
            av[i] = true;
            arp[i] = Ae + (size_t)(row0 + r)*K + c16*8;
        }
    }
    const __nv_bfloat16* brp[2]; uint32_t bOff[2];
    #pragma unroll
    for (int i = 0; i < 2; i++) {
        int r = i*32 + srow;
        bOff[i] = SMEM_SWZ((uint32_t)(r*128 + c16*16));
        brp[i] = Bte + (size_t)(col0 + r)*K + c16*8;
    }

    float c[2][4][4] = {};
    int g = lane >> 3, l7 = lane & 7;
    int nch = K >> 6;

    // stage chunk 0
    #pragma unroll
    for (int i = 0; i < 4; i++) cp16(aBase + aOff[i], arp[i], av[i]);
    #pragma unroll
    for (int i = 0; i < 2; i++) cp16(bBase + bOff[i], brp[i], true);
    CP_COMMIT();

    for (int ic = 0; ic < nch; ic++) {
        if (ic + 1 < nch) {
            int buf = (ic + 1) & 1, kc = (ic + 1) << 6;
            #pragma unroll
            for (int i = 0; i < 4; i++)
                cp16(aBase + buf*16384 + aOff[i], arp[i] + kc, av[i]);
            #pragma unroll
            for (int i = 0; i < 2; i++)
                cp16(bBase + buf*8192 + bOff[i], brp[i] + kc, true);
            CP_COMMIT();
            CP_WAIT1();
        } else {
            CP_WAIT0();
        }
        __syncthreads();
        uint32_t aB = aBase + (ic & 1)*16384;
        uint32_t bB = bBase + (ic & 1)*8192;
        #pragma unroll
        for (int ks = 0; ks < 4; ks++) {
            uint32_t a[2][4];
            #pragma unroll
            for (int mi = 0; mi < 2; mi++) {
                int r = wm*32 + mi*16 + ((g & 1) << 3) + l7;
                int kb = ks*32 + ((g >> 1) << 4);
                ldsm_x4(a[mi][0], a[mi][1], a[mi][2], a[mi][3],
                        aB + SMEM_SWZ((uint32_t)(r*128 + kb)));
            }
            uint32_t b[4][2];
            #pragma unroll
            for (int np = 0; np < 2; np++) {
                int r = wn*32 + np*16 + ((g >> 1) << 3) + l7;
                int kb = ks*32 + ((g & 1) << 4);
                uint32_t r0, r1, r2, r3;
                ldsm_x4(r0, r1, r2, r3, bB + SMEM_SWZ((uint32_t)(r*128 + kb)));
                b[np*2][0] = r0;   b[np*2][1] = r1;
                b[np*2+1][0] = r2; b[np*2+1][1] = r3;
            }
            #pragma unroll
            for (int mi = 0; mi < 2; mi++)
                #pragma unroll
                for (int nj = 0; nj < 4; nj++)
                    mma16816(c[mi][nj], a[mi][0], a[mi][1], a[mi][2], a[mi][3],
                             b[nj][0], b[nj][1]);
        }
        __syncthreads();
    }

    // ---------------- epilogue -------------------------------------------------
    int qr = lane >> 2, qc = (lane & 3) * 2;
    #pragma unroll
    for (int mi = 0; mi < 2; mi++) {
        #pragma unroll
        for (int h = 0; h < 2; h++) {
            int lr = wm*32 + mi*16 + h*8 + qr;
            #pragma unroll
            for (int nj = 0; nj < 4; nj++) {
                int col = col0 + wn*32 + nj*8 + qc;
                float v0 = c[mi][nj][2*h + 0];
                float v1 = c[mi][nj][2*h + 1];
                if (MODE == 0) {
                    size_t crow = (size_t)(row0 + lr)*ldC + col;
                    *reinterpret_cast<float2*>(Cf + crow) =
                        make_float2(v0 + be[col], v1 + be[col+1]);
                } else if (MODE == 1) {
                    if (s_tok[lr] >= 0) {
                        float h0 = v0 + be[col], h1 = v1 + be[col+1];
                        h0 = h0 * normcdff(h0);
                        h1 = h1 * normcdff(h1);
                        __nv_bfloat162 p;
                        p.x = __float2bfloat16_rn(h0); p.y = __float2bfloat16_rn(h1);
                        *reinterpret_cast<__nv_bfloat162*>(
                            g_hbuf + ((size_t)e*TTOK + row0 + lr)*384 + col) = p;
                    }
                } else {
                    int tk = s_tok[lr];
                    if (tk >= 0) {
                        float w = s_wgt[lr];
                        float* dst = (s_rnk[lr] == 0) ? g_contrib0 : g_contrib1;
                        *reinterpret_cast<float2*>(dst + (size_t)tk*192 + col) =
                            make_float2(w*(v0 + be[col]), w*(v1 + be[col+1]));
                    }
                }
            }
        }
    }
}

// ---------------- prep: sine positional encoding + zero counters ------------
__global__ void k_pos() {
    int c = threadIdx.x;
    if (c < 8) g_cnt[c] = 0;
    const float TWO_PI = 6.283185307179586f;
    const float denom = 8.0f + 1e-6f;
    int f = (c < 96) ? c : c - 96;
    float expo = (float)(f & ~1) / 96.0f;
    float dt = powf(10000.0f, expo);
    for (int n = 0; n < 64; n++) {
        int i = n >> 3, j = n & 7;
        float base = (c < 96) ? (float)(i + 1) : (float)(j + 1);
        float v = base / denom * TWO_PI / dt;
        g_pos[n*192 + c] = (f & 1) ? cosf(v) : sinf(v);
    }
}

// ------------- prep: combined (mask + rel-pos-bias) transposed table ---------
// g_bm[mw][h][m][n] = mask[mw](n,m) + bias(h, query=n, key=m); mask symmetric.
__global__ void k_bm(const float* __restrict__ mask, const float* __restrict__ rpb) {
    int mw = blockIdx.x, h = blockIdx.y;
    int n = threadIdx.x;
    int dn = n >> 6, hn = (n >> 3) & 7, wn = n & 7;
    const float* mrow = mask + (size_t)mw*16384;
    float* dst = g_bm + ((size_t)(mw*8 + h))*16384;
    for (int m = 0; m < 128; m++) {
        int dm = m >> 6, hm = (m >> 3) & 7, wm = m & 7;
        int rp = (dn - dm + 1)*225 + (hn - hm + 7)*15 + (wn - wm + 7);
        dst[m*128 + n] = mrow[m*128 + n] + rpb[rp*8 + h];
    }
}

// ---------------- prep: weight transposes -> bf16 [N][K] ---------------------
__global__ void k_transpose(const float* __restrict__ qs, const float* __restrict__ qm,
                            const float* __restrict__ pw, const float* __restrict__ W1,
                            const float* __restrict__ W2) {
    int i = blockIdx.x*blockDim.x + threadIdx.x;
    const int S1 = 576*192, S2 = 2*S1, S3 = S2 + 192*384;
    const int S4 = S3 + 8*384*192, S5 = S4 + 8*192*384;
    if (i < S1) {
        int n = i/192, k = i%192;
        g_wt_qs[i] = __float2bfloat16_rn(qs[k*576 + n]);
    } else if (i < S2) {
        int j = i - S1; int n = j/192, k = j%192;
        g_wt_qm[j] = __float2bfloat16_rn(qm[k*576 + n]);
    } else if (i < S3) {
        int j = i - S2; int n = j/384, k = j%384;
        g_wt_p[j] = __float2bfloat16_rn(pw[k*192 + n]);
    } else if (i < S4) {
        int j = i - S3; int e = j/73728, rr = j%73728;
        int n = rr/192, k = rr%192;
        g_wt_w1[j] = __float2bfloat16_rn(W1[e*73728 + k*384 + n]);
    } else if (i < S5) {
        int j = i - S4; int e = j/73728, rr = j%73728;
        int n = rr/384, k = rr%384;
        g_wt_w2[j] = __float2bfloat16_rn(W2[e*73728 + k*192 + n]);
    }
}

// ---------------- LN1 + roll + window partition -> bf16 (warp per token) -----
__global__ __launch_bounds__(256) void ln_partition(const float* __restrict__ x,
                             const float* __restrict__ w1,
                             const float* __restrict__ b1) {
    int t = (blockIdx.x*blockDim.x + threadIdx.x) >> 5;
    int lane = threadIdx.x & 31;
    int win = t >> 7, n = t & 127;
    int b_  = win / 192; int rem = win % 192;
    int dd  = rem / 64;  int rem2 = rem % 64;
    int hh  = rem2 >> 3; int ww = rem2 & 7;
    int wd  = n >> 6, wh = (n >> 3) & 7, wwp = n & 7;
    int ds = dd*2 + wd, hs = hh*8 + wh, ws = ww*8 + wwp;
    int d = ds + 1; if (d >= 6) d -= 6;
    int h = (hs + 4) & 63;
    int w = (ws + 4) & 63;
    const float* xr = x + (size_t)(((b_*6 + d)*64 + h)*64 + w)*192;
    float v[6];
    float s1 = 0.f, s2 = 0.f;
    #pragma unroll
    for (int k = 0; k < 6; k++) {
        v[k] = xr[lane + 32*k];
        s1 += v[k]; s2 += v[k]*v[k];
    }
    s1 = warpsum_all(s1); s2 = warpsum_all(s2);
    float mu  = s1 * (1.f/192.f);
    float var = s2 * (1.f/192.f) - mu*mu;
    float rstd = rsqrtf(var + 1e-5f);
    const float* pr = g_pos + (n & 63)*192;
    #pragma unroll
    for (int k = 0; k < 6; k++) {
        int cc = lane + 32*k;
        float y = (v[k] - mu) * rstd * w1[cc] + b1[cc];
        g_xw_bf[(size_t)t*192 + cc] = __float2bfloat16_rn(y);
        g_xm_bf[(size_t)t*192 + cc] = __float2bfloat16_rn(y + pr[cc]);
    }
}

// ---------------- self attention: flash-style, no score matrix ---------------
__global__ __launch_bounds__(128) void attn_self() {
    __shared__ float ks[128*25];
    __shared__ float vs[128*25];
    int win = blockIdx.x >> 3, h = blockIdx.x & 7;
    int n = threadIdx.x;
    size_t base = (size_t)(win*128 + n)*576 + h*24;
    const float4* qp = reinterpret_cast<const float4*>(g_qkv + base);
    const float4* kp = reinterpret_cast<const float4*>(g_qkv + base + 192);
    const float4* vp = reinterpret_cast<const float4*>(g_qkv + base + 384);
    float q[24];
    #pragma unroll
    for (int i = 0; i < 6; i++) {
        float4 a = qp[i];
        q[4*i+0]=a.x; q[4*i+1]=a.y; q[4*i+2]=a.z; q[4*i+3]=a.w;
        float4 b = kp[i];
        ks[n*25+4*i+0]=b.x; ks[n*25+4*i+1]=b.y; ks[n*25+4*i+2]=b.z; ks[n*25+4*i+3]=b.w;
        float4 c = vp[i];
        vs[n*25+4*i+0]=c.x; vs[n*25+4*i+1]=c.y; vs[n*25+4*i+2]=c.z; vs[n*25+4*i+3]=c.w;
    }
    __syncthreads();
    const float SC = 0.20412414523193154f;   // 24^-0.5
    const float* bm = g_bm + ((size_t)((win % 192)*8 + h))*16384;
    float o[24] = {}; float ssum = 0.f;
    #pragma unroll 2
    for (int m = 0; m < 128; m++) {
        const float* kr = ks + m*25;
        float s = 0.f;
        #pragma unroll
        for (int d = 0; d < 24; d++) s = fmaf(q[d], kr[d], s);
        s = fmaf(s, SC, bm[m*128 + n]);
        float p = __expf(s);
        ssum += p;
        const float* vr = vs + m*25;
        #pragma unroll
        for (int d = 0; d < 24; d++) o[d] = fmaf(p, vr[d], o[d]);
    }
    float inv = 1.f / ssum;
    __nv_bfloat162* ob = reinterpret_cast<__nv_bfloat162*>(
        g_xout_bf + (size_t)(win*128 + n)*384 + 192 + h*24);
    #pragma unroll
    for (int d = 0; d < 12; d++) {
        __nv_bfloat162 p;
        p.x = __float2bfloat16_rn(o[2*d]*inv);
        p.y = __float2bfloat16_rn(o[2*d+1]*inv);
        ob[d] = p;
    }
}

// ---------------- mutual attention: flash-style ------------------------------
__global__ __launch_bounds__(128) void attn_mut(const float* __restrict__ mask) {
    __shared__ float ks[2][64*25];
    __shared__ float vs[2][64*25];
    int win = blockIdx.x >> 3, h = blockIdx.x & 7;
    int tid = threadIdx.x;
    int p = tid >> 6, r = tid & 63;
    int kvtok = (p == 0) ? r : 64 + r;
    int qtok  = (p == 0) ? 64 + r : r;
    size_t kb = (size_t)(win*128 + kvtok)*576 + h*24;
    size_t qb = (size_t)(win*128 + qtok)*576 + h*24;
    const float4* qp = reinterpret_cast<const float4*>(g_qkv + qb);
    const float4* kp = reinterpret_cast<const float4*>(g_qkv + kb + 192);
    const float4* vp = reinterpret_cast<const float4*>(g_qkv + kb + 384);
    float q[24];
    #pragma unroll
    for (int i = 0; i < 6; i++) {
        float4 a = qp[i];
        q[4*i+0]=a.x; q[4*i+1]=a.y; q[4*i+2]=a.z; q[4*i+3]=a.w;
        float4 b = kp[i];
        ks[p][r*25+4*i+0]=b.x; ks[p][r*25+4*i+1]=b.y;
        ks[p][r*25+4*i+2]=b.z; ks[p][r*25+4*i+3]=b.w;
        float4 c = vp[i];
        vs[p][r*25+4*i+0]=c.x; vs[p][r*25+4*i+1]=c.y;
        vs[p][r*25+4*i+2]=c.z; vs[p][r*25+4*i+3]=c.w;
    }
    __syncthreads();
    const float SC = 0.20412414523193154f;
    const float* mrow = mask + (size_t)(win % 192)*16384;
    float o[24] = {}; float ssum = 0.f;
    #pragma unroll 2
    for (int m = 0; m < 64; m++) {
        const float* kr = ks[p] + m*25;
        float s = 0.f;
        #pragma unroll
        for (int d = 0; d < 24; d++) s = fmaf(q[d], kr[d], s);
        s = fmaf(s, SC, mrow[m*128 + r]);    // mask symmetric; coalesced over r
        float pv = __expf(s);
        ssum += pv;
        const float* vr = vs[p] + m*25;
        #pragma unroll
        for (int d = 0; d < 24; d++) o[d] = fmaf(pv, vr[d], o[d]);
    }
    float inv = 1.f / ssum;
    int orow = (p == 0) ? r : 64 + r;
    __nv_bfloat162* ob = reinterpret_cast<__nv_bfloat162*>(
        g_xout_bf + (size_t)(win*128 + orow)*384 + h*24);
    #pragma unroll
    for (int d = 0; d < 12; d++) {
        __nv_bfloat162 pr;
        pr.x = __float2bfloat16_rn(o[2*d]*inv);
        pr.y = __float2bfloat16_rn(o[2*d+1]*inv);
        ob[d] = pr;
    }
}

// --------- residual scatter + LN2 + gate top-2 (warp per token) --------------
__global__ __launch_bounds__(256) void resid_gate(const float* __restrict__ x,
                           const float* __restrict__ n2w, const float* __restrict__ n2b,
                           const float* __restrict__ gw,  const float* __restrict__ gb) {
    __shared__ float s_gw[8*192];        // [j][c]
    for (int i = threadIdx.x; i < 1536; i += 256) {
        int j = i / 192, cc = i % 192;
        s_gw[i] = gw[cc*8 + j];
    }
    __syncthreads();
    int t = (blockIdx.x*blockDim.x + threadIdx.x) >> 5;
    int lane = threadIdx.x & 31;
    int b_ = t / 24576; int rrem = t % 24576;
    int d  = rrem / 4096; int r2 = rrem % 4096;
    int hh_ = r2 / 64; int ww_ = r2 % 64;
    int ds = d - 1; if (ds < 0) ds += 6;
    int hs = (hh_ + 60) & 63;
    int ws = (ww_ + 60) & 63;
    int dd = ds >> 1, wd = ds & 1;
    int hblk = hs >> 3, wh = hs & 7;
    int wblk = ws >> 3, wwp = ws & 7;
    int win = ((b_*3 + dd)*8 + hblk)*8 + wblk;
    int n = wd*64 + wh*8 + wwp;
    const float* ar = g_attnbuf + (size_t)(win*128 + n)*192;
    const float* xr = x + (size_t)t*192;
    float v[6];
    float s1 = 0.f, s2 = 0.f;
    #pragma unroll
    for (int k = 0; k < 6; k++) {
        int cc = lane + 32*k;
        v[k] = xr[cc] + ar[cc];
        g_xres[(size_t)t*192 + cc] = v[k];
        s1 += v[k]; s2 += v[k]*v[k];
    }
    s1 = warpsum_all(s1); s2 = warpsum_all(s2);
    float mu  = s1 * (1.f/192.f);
    float var = s2 * (1.f/192.f) - mu*mu;
    float rstd = rsqrtf(var + 1e-5f);
    float g[8] = {};
    #pragma unroll
    for (int k = 0; k < 6; k++) {
        int cc = lane + 32*k;
        float xn = (v[k] - mu) * rstd * n2w[cc] + n2b[cc];
        g_xn2_bf[(size_t)t*192 + cc] = __float2bfloat16_rn(xn);
        #pragma unroll
        for (int j = 0; j < 8; j++) g[j] = fmaf(xn, s_gw[j*192 + cc], g[j]);
    }
    #pragma unroll
    for (int j = 0; j < 8; j++) g[j] = warpsum_all(g[j]);
    if (lane == 0) {
        float L[8];
        #pragma unroll
        for (int j = 0; j < 8; j++) L[j] = g[j] + gb[j];
        int e0 = 0;
        #pragma unroll
        for (int j = 1; j < 8; j++) if (L[j] > L[e0]) e0 = j;
        int e1 = (e0 == 0) ? 1 : 0;
        #pragma unroll
        for (int j = 0; j < 8; j++) if (j != e0 && L[j] > L[e1]) e1 = j;
        float w0 = 1.f / (1.f + __expf(L[e1] - L[e0]));
        float w1 = 1.f - w0;
        int p0 = atomicAdd(&g_cnt[e0], 1);
        g_gidx[e0*TTOK + p0] = t; g_gw[e0*TTOK + p0] = w0; g_grank[e0*TTOK + p0] = 0;
        int p1 = atomicAdd(&g_cnt[e1], 1);
        g_gidx[e1*TTOK + p1] = t; g_gw[e1*TTOK + p1] = w1; g_grank[e1*TTOK + p1] = 1;
    }
}

// ---------------- finalize ----------------------------------------------------
__global__ void finalize(float* __restrict__ out) {
    int i = blockIdx.x*blockDim.x + threadIdx.x;
    if (i < TTOK*48) {
        float4 a  = reinterpret_cast<const float4*>(g_xres)[i];
        float4 c0 = reinterpret_cast<const float4*>(g_contrib0)[i];
        float4 c1 = reinterpret_cast<const float4*>(g_contrib1)[i];
        reinterpret_cast<float4*>(out)[i] =
            make_float4(a.x + c0.x + c1.x, a.y + c0.y + c1.y,
                        a.z + c0.z + c1.z, a.w + c0.w + c1.w);
    }
}

// ---------------- host launcher -----------------------------------------------
extern "C" void kernel_launch(void* const* d_in, const int* in_sizes, int n_in,
                              void* d_out, int out_size) {
    const float* x    = (const float*)d_in[0];
    const float* mask = (const float*)d_in[1];
    const float* n1w  = (const float*)d_in[2];
    const float* n1b  = (const float*)d_in[3];
    const float* qsw  = (const float*)d_in[4];
    const float* qsb  = (const float*)d_in[5];
    const float* qmw  = (const float*)d_in[6];
    const float* qmb  = (const float*)d_in[7];
    const float* rpb  = (const float*)d_in[8];
    const float* pw   = (const float*)d_in[9];
    const float* pb   = (const float*)d_in[10];
    const float* n2w  = (const float*)d_in[11];
    const float* n2b  = (const float*)d_in[12];
    const float* gw   = (const float*)d_in[13];
    const float* gb   = (const float*)d_in[14];
    const float* W1   = (const float*)d_in[15];
    const float* b1   = (const float*)d_in[16];
    const float* W2   = (const float*)d_in[17];
    const float* b2   = (const float*)d_in[18];
    float* out = (float*)d_out;

    const int DSMEM = 50176;   // 48KB tiles + 1KB alignment pad
    cudaFuncSetAttribute(gemm_mma<0>, cudaFuncAttributeMaxDynamicSharedMemorySize, DSMEM);
    cudaFuncSetAttribute(gemm_mma<1>, cudaFuncAttributeMaxDynamicSharedMemorySize, DSMEM);
    cudaFuncSetAttribute(gemm_mma<2>, cudaFuncAttributeMaxDynamicSharedMemorySize, DSMEM);

    void *p_xw, *p_xm, *p_xout, *p_xn2, *p_h, *p_qkv, *p_attn;
    void *p_wqs, *p_wqm, *p_wp, *p_w1, *p_w2;
    cudaGetSymbolAddress(&p_xw,  g_xw_bf);
    cudaGetSymbolAddress(&p_xm,  g_xm_bf);
    cudaGetSymbolAddress(&p_xout,g_xout_bf);
    cudaGetSymbolAddress(&p_xn2, g_xn2_bf);
    cudaGetSymbolAddress(&p_h,   g_hbuf);
    cudaGetSymbolAddress(&p_qkv, g_qkv);
    cudaGetSymbolAddress(&p_attn,g_attnbuf);
    cudaGetSymbolAddress(&p_wqs, g_wt_qs);
    cudaGetSymbolAddress(&p_wqm, g_wt_qm);
    cudaGetSymbolAddress(&p_wp,  g_wt_p);
    cudaGetSymbolAddress(&p_w1,  g_wt_w1);
    cudaGetSymbolAddress(&p_w2,  g_wt_w2);

    k_pos<<<1, 192>>>();
    k_bm<<<dim3(192, 8), 128>>>(mask, rpb);
    k_transpose<<<5760, 256>>>(qsw, qmw, pw, W1, W2);
    ln_partition<<<6144, 256>>>(x, n1w, n1b);
    gemm_mma<0><<<dim3(384, 9), 256, DSMEM>>>((const __nv_bfloat16*)p_xw,
        (const __nv_bfloat16*)p_wqs, qsb, (float*)p_qkv, 192, 576);
    attn_self<<<NWIN*8, 128>>>();
    gemm_mma<0><<<dim3(384, 9), 256, DSMEM>>>((const __nv_bfloat16*)p_xm,
        (const __nv_bfloat16*)p_wqm, qmb, (float*)p_qkv, 192, 576);
    attn_mut<<<NWIN*8, 128>>>(mask);
    gemm_mma<0><<<dim3(384, 3), 256, DSMEM>>>((const __nv_bfloat16*)p_xout,
        (const __nv_bfloat16*)p_wp, pb, (float*)p_attn, 384, 192);
    resid_gate<<<6144, 256>>>(x, n2w, n2b, gw, gb);
    gemm_mma<1><<<dim3(384, 6, 8), 256, DSMEM>>>((const __nv_bfloat16*)p_xn2,
        (const __nv_bfloat16*)p_w1, b1, nullptr, 192, 384);
    gemm_mma<2><<<dim3(384, 3, 8), 256, DSMEM>>>((const __nv_bfloat16*)p_h,
        (const __nv_bfloat16*)p_w2, b2, nullptr, 384, 192);
    finalize<<<9216, 256>>>(out);
}

// round 5
// speedup vs baseline: 7.5615x; 1.2135x over previous
#include <cuda_runtime.h>
#include <cuda_bf16.h>
#include <math.h>
#include <cstdint>

#define TTOK 49152      // total tokens = 2*6*64*64
#define NWIN 384

// ---------------- scratch (device globals; no allocations allowed) ----------
__device__ float g_qkv[TTOK*576];       // qkv fp32 (reused self & mutual)
__device__ float g_attnbuf[TTOK*192];   // proj output (window order)
__device__ float g_xres[TTOK*192];      // x + attn residual (original order)
__device__ float g_pos[64*192];
__device__ float g_biasf[8*128*128];    // rel-pos bias per head [h][m_key][n_query]
__device__ int   g_cnt[8];
__device__ int   g_gidx[8*TTOK];
__device__ float g_gw[8*TTOK];
__device__ int   g_grank[8*TTOK];
__device__ float g_contrib0[TTOK*192];
__device__ float g_contrib1[TTOK*192];
// bf16 activation buffers for tensor-core GEMMs
__device__ __nv_bfloat16 g_xw_bf[TTOK*192];
__device__ __nv_bfloat16 g_xm_bf[TTOK*192];
__device__ __nv_bfloat16 g_xout_bf[TTOK*384];
__device__ __nv_bfloat16 g_xn2_bf[TTOK*192];
__device__ __nv_bfloat16 g_hbuf[(size_t)8*TTOK*384];
// transposed bf16 weights [N][K]
__device__ __nv_bfloat16 g_wt_qs[576*192];
__device__ __nv_bfloat16 g_wt_qm[576*192];
__device__ __nv_bfloat16 g_wt_p [192*384];
__device__ __nv_bfloat16 g_wt_w1[8*384*192];
__device__ __nv_bfloat16 g_wt_w2[8*192*384];

// ---------------- helpers ------------------------------------------------
typedef unsigned long long ull;
__device__ __forceinline__ float warpsum_all(float v) {
    #pragma unroll
    for (int o = 16; o; o >>= 1) v += __shfl_xor_sync(0xffffffffu, v, o);
    return v;
}
__device__ __forceinline__ uint32_t smem_u32(const void* p) {
    uint32_t a;
    asm("{ .reg .u64 t; cvta.to.shared.u64 t, %1; cvt.u32.u64 %0, t; }" : "=r"(a) : "l"(p));
    return a;
}
__device__ __forceinline__ void ldsm_x4(uint32_t& r0, uint32_t& r1, uint32_t& r2,
                                        uint32_t& r3, uint32_t addr) {
    asm volatile("ldmatrix.sync.aligned.m8n8.x4.shared.b16 {%0,%1,%2,%3}, [%4];"
                 : "=r"(r0), "=r"(r1), "=r"(r2), "=r"(r3) : "r"(addr));
}
__device__ __forceinline__ void mma16816(float* c, uint32_t a0, uint32_t a1,
                                         uint32_t a2, uint32_t a3,
                                         uint32_t b0, uint32_t b1) {
    asm volatile("mma.sync.aligned.m16n8k16.row.col.f32.bf16.bf16.f32 "
        "{%0,%1,%2,%3}, {%4,%5,%6,%7}, {%8,%9}, {%0,%1,%2,%3};"
        : "+f"(c[0]), "+f"(c[1]), "+f"(c[2]), "+f"(c[3])
        : "r"(a0), "r"(a1), "r"(a2), "r"(a3), "r"(b0), "r"(b1));
}
__device__ __forceinline__ void cp16(uint32_t dst, const void* src, bool v) {
    asm volatile("cp.async.cg.shared.global [%0], [%1], 16, %2;"
                 :: "r"(dst), "l"(src), "r"(v ? 16u : 0u));
}
#define CP_COMMIT() asm volatile("cp.async.commit_group;")
#define CP_WAIT1()  asm volatile("cp.async.wait_group 1;")
#define CP_WAIT0()  asm volatile("cp.async.wait_group 0;")
#define SMEM_SWZ(o) ((o) ^ (((o) >> 3) & 0x70))

// ---- packed f32x2 ops (Blackwell FFMA2) ----
__device__ __forceinline__ ull fma2(ull a, ull b, ull c) {
    ull d;
    asm("fma.rn.f32x2 %0, %1, %2, %3;" : "=l"(d) : "l"(a), "l"(b), "l"(c));
    return d;
}
__device__ __forceinline__ ull pack2(float x, float y) {
    ull r;
    asm("mov.b64 %0, {%1,%2};" : "=l"(r) : "f"(x), "f"(y));
    return r;
}
__device__ __forceinline__ float2 unpack2(ull v) {
    float x, y;
    asm("mov.b64 {%0,%1}, %2;" : "=f"(x), "=f"(y) : "l"(v));
    return make_float2(x, y);
}

// ================= bf16 HMMA GEMM: block tile 128 x 64, cp.async 2-stage ====
template<int MODE>
__global__ __launch_bounds__(256) void gemm_mma(
        const __nv_bfloat16* __restrict__ A,
        const __nv_bfloat16* __restrict__ Bt,
        const float* __restrict__ bias,
        float* __restrict__ Cf, int K, int ldC) {
    extern __shared__ uint8_t dyn_raw[];
    __shared__ int s_tok[128]; __shared__ float s_wgt[128]; __shared__ int s_rnk[128];

    int tid = threadIdx.x, wid = tid >> 5, lane = tid & 31;
    int wm = wid >> 1, wn = wid & 1;
    int row0 = blockIdx.x * 128, col0 = blockIdx.y * 64;
    int e = blockIdx.z;
    int cnt = TTOK;
    if (MODE != 0) { cnt = g_cnt[e]; if (row0 >= cnt) return; }
    const __nv_bfloat16* Bte = Bt + (size_t)e * ldC * K;
    const float* be = bias + (size_t)e * ldC;
    const __nv_bfloat16* Ae = (MODE == 2) ? (A + (size_t)e * TTOK * K) : A;

    if (MODE != 0 && tid < 128) {
        int slot = row0 + tid;
        if (slot < cnt) {
            s_tok[tid] = g_gidx[e*TTOK + slot];
            s_wgt[tid] = g_gw[e*TTOK + slot];
            s_rnk[tid] = g_grank[e*TTOK + slot];
        } else s_tok[tid] = -1;
    }
    if (MODE != 0) __syncthreads();

    uint32_t aBase = (smem_u32(dyn_raw) + 1023u) & ~1023u;
    uint32_t bBase = aBase + 32768;

    int srow = tid >> 3, c16 = tid & 7;
    const __nv_bfloat16* arp[4]; bool av[4]; uint32_t aOff[4];
    #pragma unroll
    for (int i = 0; i < 4; i++) {
        int r = i*32 + srow;
        aOff[i] = SMEM_SWZ((uint32_t)(r*128 + c16*16));
        if (MODE == 1) {
            int tk = s_tok[r];
            av[i] = (tk >= 0);
            arp[i] = Ae + (size_t)(av[i] ? tk : 0)*K + c16*8;
        } else if (MODE == 2) {
            av[i] = (row0 + r < cnt);
            arp[i] = Ae + (size_t)(av[i] ? (row0 + r) : 0)*K + c16*8;
        } else {
            av[i] = true;
            arp[i] = Ae + (size_t)(row0 + r)*K + c16*8;
        }
    }
    const __nv_bfloat16* brp[2]; uint32_t bOff[2];
    #pragma unroll
    for (int i = 0; i < 2; i++) {
        int r = i*32 + srow;
        bOff[i] = SMEM_SWZ((uint32_t)(r*128 + c16*16));
        brp[i] = Bte + (size_t)(col0 + r)*K + c16*8;
    }

    float c[2][4][4] = {};
    int g = lane >> 3, l7 = lane & 7;
    int nch = K >> 6;

    #pragma unroll
    for (int i = 0; i < 4; i++) cp16(aBase + aOff[i], arp[i], av[i]);
    #pragma unroll
    for (int i = 0; i < 2; i++) cp16(bBase + bOff[i], brp[i], true);
    CP_COMMIT();

    for (int ic = 0; ic < nch; ic++) {
        if (ic + 1 < nch) {
            int buf = (ic + 1) & 1, kc = (ic + 1) << 6;
            #pragma unroll
            for (int i = 0; i < 4; i++)
                cp16(aBase + buf*16384 + aOff[i], arp[i] + kc, av[i]);
            #pragma unroll
            for (int i = 0; i < 2; i++)
                cp16(bBase + buf*8192 + bOff[i], brp[i] + kc, true);
            CP_COMMIT();
            CP_WAIT1();
        } else {
            CP_WAIT0();
        }
        __syncthreads();
        uint32_t aB = aBase + (ic & 1)*16384;
        uint32_t bB = bBase + (ic & 1)*8192;
        #pragma unroll
        for (int ks = 0; ks < 4; ks++) {
            uint32_t a[2][4];
            #pragma unroll
            for (int mi = 0; mi < 2; mi++) {
                int r = wm*32 + mi*16 + ((g & 1) << 3) + l7;
                int kb = ks*32 + ((g >> 1) << 4);
                ldsm_x4(a[mi][0], a[mi][1], a[mi][2], a[mi][3],
                        aB + SMEM_SWZ((uint32_t)(r*128 + kb)));
            }
            uint32_t b[4][2];
            #pragma unroll
            for (int np = 0; np < 2; np++) {
                int r = wn*32 + np*16 + ((g >> 1) << 3) + l7;
                int kb = ks*32 + ((g & 1) << 4);
                uint32_t r0, r1, r2, r3;
                ldsm_x4(r0, r1, r2, r3, bB + SMEM_SWZ((uint32_t)(r*128 + kb)));
                b[np*2][0] = r0;   b[np*2][1] = r1;
                b[np*2+1][0] = r2; b[np*2+1][1] = r3;
            }
            #pragma unroll
            for (int mi = 0; mi < 2; mi++)
                #pragma unroll
                for (int nj = 0; nj < 4; nj++)
                    mma16816(c[mi][nj], a[mi][0], a[mi][1], a[mi][2], a[mi][3],
                             b[nj][0], b[nj][1]);
        }
        __syncthreads();
    }

    int qr = lane >> 2, qc = (lane & 3) * 2;
    #pragma unroll
    for (int mi = 0; mi < 2; mi++) {
        #pragma unroll
        for (int h = 0; h < 2; h++) {
            int lr = wm*32 + mi*16 + h*8 + qr;
            #pragma unroll
            for (int nj = 0; nj < 4; nj++) {
                int col = col0 + wn*32 + nj*8 + qc;
                float v0 = c[mi][nj][2*h + 0];
                float v1 = c[mi][nj][2*h + 1];
                if (MODE == 0) {
                    size_t crow = (size_t)(row0 + lr)*ldC + col;
                    *reinterpret_cast<float2*>(Cf + crow) =
                        make_float2(v0 + be[col], v1 + be[col+1]);
                } else if (MODE == 1) {
                    if (s_tok[lr] >= 0) {
                        float h0 = v0 + be[col], h1 = v1 + be[col+1];
                        h0 = h0 * normcdff(h0);
                        h1 = h1 * normcdff(h1);
                        __nv_bfloat162 p;
                        p.x = __float2bfloat16_rn(h0); p.y = __float2bfloat16_rn(h1);
                        *reinterpret_cast<__nv_bfloat162*>(
                            g_hbuf + ((size_t)e*TTOK + row0 + lr)*384 + col) = p;
                    }
                } else {
                    int tk = s_tok[lr];
                    if (tk >= 0) {
                        float w = s_wgt[lr];
                        float* dst = (s_rnk[lr] == 0) ? g_contrib0 : g_contrib1;
                        *reinterpret_cast<float2*>(dst + (size_t)tk*192 + col) =
                            make_float2(w*(v0 + be[col]), w*(v1 + be[col+1]));
                    }
                }
            }
        }
    }
}

// ---------------- prep: sine positional encoding + zero counters ------------
__global__ void k_pos() {
    int c = threadIdx.x;
    if (c < 8) g_cnt[c] = 0;
    const float TWO_PI = 6.283185307179586f;
    const float denom = 8.0f + 1e-6f;
    int f = (c < 96) ? c : c - 96;
    float expo = (float)(f & ~1) / 96.0f;
    float dt = powf(10000.0f, expo);
    for (int n = 0; n < 64; n++) {
        int i = n >> 3, j = n & 7;
        float base = (c < 96) ? (float)(i + 1) : (float)(j + 1);
        float v = base / denom * TWO_PI / dt;
        g_pos[n*192 + c] = (f & 1) ? cosf(v) : sinf(v);
    }
}

// ---------------- prep: rel-pos bias table [h][m_key][n_query] ---------------
__global__ void k_bias(const float* __restrict__ rpb) {
    int m = blockIdx.x, n = threadIdx.x;         // m = key, n = query
    int dn = n >> 6, hn = (n >> 3) & 7, wn = n & 7;
    int dm = m >> 6, hm = (m >> 3) & 7, wm = m & 7;
    int rp = (dn - dm + 1)*225 + (hn - hm + 7)*15 + (wn - wm + 7);
    #pragma unroll
    for (int h = 0; h < 8; h++)
        g_biasf[h*16384 + m*128 + n] = rpb[rp*8 + h];
}

// ---------------- prep: weight transposes -> bf16 [N][K] ---------------------
__global__ void k_transpose(const float* __restrict__ qs, const float* __restrict__ qm,
                            const float* __restrict__ pw, const float* __restrict__ W1,
                            const float* __restrict__ W2) {
    int i = blockIdx.x*blockDim.x + threadIdx.x;
    const int S1 = 576*192, S2 = 2*S1, S3 = S2 + 192*384;
    const int S4 = S3 + 8*384*192, S5 = S4 + 8*192*384;
    if (i < S1) {
        int n = i/192, k = i%192;
        g_wt_qs[i] = __float2bfloat16_rn(qs[k*576 + n]);
    } else if (i < S2) {
        int j = i - S1; int n = j/192, k = j%192;
        g_wt_qm[j] = __float2bfloat16_rn(qm[k*576 + n]);
    } else if (i < S3) {
        int j = i - S2; int n = j/384, k = j%384;
        g_wt_p[j] = __float2bfloat16_rn(pw[k*192 + n]);
    } else if (i < S4) {
        int j = i - S3; int e = j/73728, rr = j%73728;
        int n = rr/192, k = rr%192;
        g_wt_w1[j] = __float2bfloat16_rn(W1[e*73728 + k*384 + n]);
    } else if (i < S5) {
        int j = i - S4; int e = j/73728, rr = j%73728;
        int n = rr/384, k = rr%384;
        g_wt_w2[j] = __float2bfloat16_rn(W2[e*73728 + k*192 + n]);
    }
}

// ---------------- LN1 + roll + window partition -> bf16 (warp per token) -----
__global__ __launch_bounds__(256) void ln_partition(const float* __restrict__ x,
                             const float* __restrict__ w1,
                             const float* __restrict__ b1) {
    int t = (blockIdx.x*blockDim.x + threadIdx.x) >> 5;
    int lane = threadIdx.x & 31;
    int win = t >> 7, n = t & 127;
    int b_  = win / 192; int rem = win % 192;
    int dd  = rem / 64;  int rem2 = rem % 64;
    int hh  = rem2 >> 3; int ww = rem2 & 7;
    int wd  = n >> 6, wh = (n >> 3) & 7, wwp = n & 7;
    int ds = dd*2 + wd, hs = hh*8 + wh, ws = ww*8 + wwp;
    int d = ds + 1; if (d >= 6) d -= 6;
    int h = (hs + 4) & 63;
    int w = (ws + 4) & 63;
    const float* xr = x + (size_t)(((b_*6 + d)*64 + h)*64 + w)*192;
    float v[6];
    float s1 = 0.f, s2 = 0.f;
    #pragma unroll
    for (int k = 0; k < 6; k++) {
        v[k] = xr[lane + 32*k];
        s1 += v[k]; s2 += v[k]*v[k];
    }
    s1 = warpsum_all(s1); s2 = warpsum_all(s2);
    float mu  = s1 * (1.f/192.f);
    float var = s2 * (1.f/192.f) - mu*mu;
    float rstd = rsqrtf(var + 1e-5f);
    const float* pr = g_pos + (n & 63)*192;
    #pragma unroll
    for (int k = 0; k < 6; k++) {
        int cc = lane + 32*k;
        float y = (v[k] - mu) * rstd * w1[cc] + b1[cc];
        g_xw_bf[(size_t)t*192 + cc] = __float2bfloat16_rn(y);
        g_xm_bf[(size_t)t*192 + cc] = __float2bfloat16_rn(y + pr[cc]);
    }
}

// ---------------- self attention: flash-style, packed f32x2 ------------------
#define KVS 28   // padded row stride (floats): 112B, 16B-aligned rows
__global__ __launch_bounds__(128) void attn_self(const float* __restrict__ mask) {
    __shared__ __align__(16) float ks[128*KVS];
    __shared__ __align__(16) float vs[128*KVS];
    int win = blockIdx.x >> 3, h = blockIdx.x & 7;
    int n = threadIdx.x;
    size_t base = (size_t)(win*128 + n)*576 + h*24;
    const float4* qp = reinterpret_cast<const float4*>(g_qkv + base);
    const float4* kp = reinterpret_cast<const float4*>(g_qkv + base + 192);
    const float4* vp = reinterpret_cast<const float4*>(g_qkv + base + 384);
    const float SC = 0.20412414523193154f;   // 24^-0.5
    ull q2[12];
    #pragma unroll
    for (int i = 0; i < 6; i++) {
        float4 a = qp[i];
        q2[2*i]   = pack2(a.x*SC, a.y*SC);
        q2[2*i+1] = pack2(a.z*SC, a.w*SC);
        *reinterpret_cast<float4*>(&ks[n*KVS + 4*i]) = kp[i];
        *reinterpret_cast<float4*>(&vs[n*KVS + 4*i]) = vp[i];
    }
    __syncthreads();
    const float* mrow = mask + (size_t)(win % 192)*16384;
    const float* brow = g_biasf + (size_t)h*16384;
    ull o2[12] = {};
    float ssum = 0.f;
    #pragma unroll 2
    for (int m = 0; m < 128; m++) {
        const ull* kr = reinterpret_cast<const ull*>(ks + m*KVS);
        ull acc = 0ull;
        #pragma unroll
        for (int i = 0; i < 12; i++) acc = fma2(q2[i], kr[i], acc);
        float2 ac = unpack2(acc);
        float s = ac.x + ac.y + mrow[m*128 + n] + brow[m*128 + n];
        float p = __expf(s);
        ssum += p;
        ull pp = pack2(p, p);
        const ull* vr = reinterpret_cast<const ull*>(vs + m*KVS);
        #pragma unroll
        for (int i = 0; i < 12; i++) o2[i] = fma2(vr[i], pp, o2[i]);
    }
    float inv = 1.f / ssum;
    __nv_bfloat162* ob = reinterpret_cast<__nv_bfloat162*>(
        g_xout_bf + (size_t)(win*128 + n)*384 + 192 + h*24);
    #pragma unroll
    for (int i = 0; i < 12; i++) {
        float2 o = unpack2(o2[i]);
        __nv_bfloat162 p;
        p.x = __float2bfloat16_rn(o.x*inv);
        p.y = __float2bfloat16_rn(o.y*inv);
        ob[i] = p;
    }
}

// ---------------- mutual attention: flash-style, packed f32x2 ----------------
__global__ __launch_bounds__(128) void attn_mut(const float* __restrict__ mask) {
    __shared__ __align__(16) float ks[2][64*KVS];
    __shared__ __align__(16) float vs[2][64*KVS];
    int win = blockIdx.x >> 3, h = blockIdx.x & 7;
    int tid = threadIdx.x;
    int p = tid >> 6, r = tid & 63;
    int kvtok = (p == 0) ? r : 64 + r;
    int qtok  = (p == 0) ? 64 + r : r;
    size_t kb = (size_t)(win*128 + kvtok)*576 + h*24;
    size_t qb = (size_t)(win*128 + qtok)*576 + h*24;
    const float4* qp = reinterpret_cast<const float4*>(g_qkv + qb);
    const float4* kp = reinterpret_cast<const float4*>(g_qkv + kb + 192);
    const float4* vp = reinterpret_cast<const float4*>(g_qkv + kb + 384);
    const float SC = 0.20412414523193154f;
    ull q2[12];
    #pragma unroll
    for (int i = 0; i < 6; i++) {
        float4 a = qp[i];
        q2[2*i]   = pack2(a.x*SC, a.y*SC);
        q2[2*i+1] = pack2(a.z*SC, a.w*SC);
        *reinterpret_cast<float4*>(&ks[p][r*KVS + 4*i]) = kp[i];
        *reinterpret_cast<float4*>(&vs[p][r*KVS + 4*i]) = vp[i];
    }
    __syncthreads();
    const float* mrow = mask + (size_t)(win % 192)*16384;
    ull o2[12] = {};
    float ssum = 0.f;
    #pragma unroll 2
    for (int m = 0; m < 64; m++) {
        const ull* kr = reinterpret_cast<const ull*>(&ks[p][m*KVS]);
        ull acc = 0ull;
        #pragma unroll
        for (int i = 0; i < 12; i++) acc = fma2(q2[i], kr[i], acc);
        float2 ac = unpack2(acc);
        float s = ac.x + ac.y + mrow[m*128 + r];   // mask symmetric
        float pv = __expf(s);
        ssum += pv;
        ull pp = pack2(pv, pv);
        const ull* vr = reinterpret_cast<const ull*>(&vs[p][m*KVS]);
        #pragma unroll
        for (int i = 0; i < 12; i++) o2[i] = fma2(vr[i], pp, o2[i]);
    }
    float inv = 1.f / ssum;
    int orow = (p == 0) ? r : 64 + r;
    __nv_bfloat162* ob = reinterpret_cast<__nv_bfloat162*>(
        g_xout_bf + (size_t)(win*128 + orow)*384 + h*24);
    #pragma unroll
    for (int i = 0; i < 12; i++) {
        float2 o = unpack2(o2[i]);
        __nv_bfloat162 pr;
        pr.x = __float2bfloat16_rn(o.x*inv);
        pr.y = __float2bfloat16_rn(o.y*inv);
        ob[i] = pr;
    }
}

// --------- residual scatter + LN2 + gate top-2 (warp per token) --------------
__global__ __launch_bounds__(256) void resid_gate(const float* __restrict__ x,
                           const float* __restrict__ n2w, const float* __restrict__ n2b,
                           const float* __restrict__ gw,  const float* __restrict__ gb) {
    __shared__ float s_gw[8*192];
    for (int i = threadIdx.x; i < 1536; i += 256) {
        int j = i / 192, cc = i % 192;
        s_gw[i] = gw[cc*8 + j];
    }
    __syncthreads();
    int t = (blockIdx.x*blockDim.x + threadIdx.x) >> 5;
    int lane = threadIdx.x & 31;
    int b_ = t / 24576; int rrem = t % 24576;
    int d  = rrem / 4096; int r2 = rrem % 4096;
    int hh_ = r2 / 64; int ww_ = r2 % 64;
    int ds = d - 1; if (ds < 0) ds += 6;
    int hs = (hh_ + 60) & 63;
    int ws = (ww_ + 60) & 63;
    int dd = ds >> 1, wd = ds & 1;
    int hblk = hs >> 3, wh = hs & 7;
    int wblk = ws >> 3, wwp = ws & 7;
    int win = ((b_*3 + dd)*8 + hblk)*8 + wblk;
    int n = wd*64 + wh*8 + wwp;
    const float* ar = g_attnbuf + (size_t)(win*128 + n)*192;
    const float* xr = x + (size_t)t*192;
    float v[6];
    float s1 = 0.f, s2 = 0.f;
    #pragma unroll
    for (int k = 0; k < 6; k++) {
        int cc = lane + 32*k;
        v[k] = xr[cc] + ar[cc];
        g_xres[(size_t)t*192 + cc] = v[k];
        s1 += v[k]; s2 += v[k]*v[k];
    }
    s1 = warpsum_all(s1); s2 = warpsum_all(s2);
    float mu  = s1 * (1.f/192.f);
    float var = s2 * (1.f/192.f) - mu*mu;
    float rstd = rsqrtf(var + 1e-5f);
    float g[8] = {};
    #pragma unroll
    for (int k = 0; k < 6; k++) {
        int cc = lane + 32*k;
        float xn = (v[k] - mu) * rstd * n2w[cc] + n2b[cc];
        g_xn2_bf[(size_t)t*192 + cc] = __float2bfloat16_rn(xn);
        #pragma unroll
        for (int j = 0; j < 8; j++) g[j] = fmaf(xn, s_gw[j*192 + cc], g[j]);
    }
    #pragma unroll
    for (int j = 0; j < 8; j++) g[j] = warpsum_all(g[j]);
    if (lane == 0) {
        float L[8];
        #pragma unroll
        for (int j = 0; j < 8; j++) L[j] = g[j] + gb[j];
        int e0 = 0;
        #pragma unroll
        for (int j = 1; j < 8; j++) if (L[j] > L[e0]) e0 = j;
        int e1 = (e0 == 0) ? 1 : 0;
        #pragma unroll
        for (int j = 0; j < 8; j++) if (j != e0 && L[j] > L[e1]) e1 = j;
        float w0 = 1.f / (1.f + __expf(L[e1] - L[e0]));
        float w1 = 1.f - w0;
        int p0 = atomicAdd(&g_cnt[e0], 1);
        g_gidx[e0*TTOK + p0] = t; g_gw[e0*TTOK + p0] = w0; g_grank[e0*TTOK + p0] = 0;
        int p1 = atomicAdd(&g_cnt[e1], 1);
        g_gidx[e1*TTOK + p1] = t; g_gw[e1*TTOK + p1] = w1; g_grank[e1*TTOK + p1] = 1;
    }
}

// ---------------- finalize ----------------------------------------------------
__global__ void finalize(float* __restrict__ out) {
    int i = blockIdx.x*blockDim.x + threadIdx.x;
    if (i < TTOK*48) {
        float4 a  = reinterpret_cast<const float4*>(g_xres)[i];
        float4 c0 = reinterpret_cast<const float4*>(g_contrib0)[i];
        float4 c1 = reinterpret_cast<const float4*>(g_contrib1)[i];
        reinterpret_cast<float4*>(out)[i] =
            make_float4(a.x + c0.x + c1.x, a.y + c0.y + c1.y,
                        a.z + c0.z + c1.z, a.w + c0.w + c1.w);
    }
}

// ---------------- host launcher -----------------------------------------------
extern "C" void kernel_launch(void* const* d_in, const int* in_sizes, int n_in,
                              void* d_out, int out_size) {
    const float* x    = (const float*)d_in[0];
    const float* mask = (const float*)d_in[1];
    const float* n1w  = (const float*)d_in[2];
    const float* n1b  = (const float*)d_in[3];
    const float* qsw  = (const float*)d_in[4];
    const float* qsb  = (const float*)d_in[5];
    const float* qmw  = (const float*)d_in[6];
    const float* qmb  = (const float*)d_in[7];
    const float* rpb  = (const float*)d_in[8];
    const float* pw   = (const float*)d_in[9];
    const float* pb   = (const float*)d_in[10];
    const float* n2w  = (const float*)d_in[11];
    const float* n2b  = (const float*)d_in[12];
    const float* gw   = (const float*)d_in[13];
    const float* gb   = (const float*)d_in[14];
    const float* W1   = (const float*)d_in[15];
    const float* b1   = (const float*)d_in[16];
    const float* W2   = (const float*)d_in[17];
    const float* b2   = (const float*)d_in[18];
    float* out = (float*)d_out;

    const int DSMEM = 50176;
    cudaFuncSetAttribute(gemm_mma<0>, cudaFuncAttributeMaxDynamicSharedMemorySize, DSMEM);
    cudaFuncSetAttribute(gemm_mma<1>, cudaFuncAttributeMaxDynamicSharedMemorySize, DSMEM);
    cudaFuncSetAttribute(gemm_mma<2>, cudaFuncAttributeMaxDynamicSharedMemorySize, DSMEM);

    void *p_xw, *p_xm, *p_xout, *p_xn2, *p_h, *p_qkv, *p_attn;
    void *p_wqs, *p_wqm, *p_wp, *p_w1, *p_w2;
    cudaGetSymbolAddress(&p_xw,  g_xw_bf);
    cudaGetSymbolAddress(&p_xm,  g_xm_bf);
    cudaGetSymbolAddress(&p_xout,g_xout_bf);
    cudaGetSymbolAddress(&p_xn2, g_xn2_bf);
    cudaGetSymbolAddress(&p_h,   g_hbuf);
    cudaGetSymbolAddress(&p_qkv, g_qkv);
    cudaGetSymbolAddress(&p_attn,g_attnbuf);
    cudaGetSymbolAddress(&p_wqs, g_wt_qs);
    cudaGetSymbolAddress(&p_wqm, g_wt_qm);
    cudaGetSymbolAddress(&p_wp,  g_wt_p);
    cudaGetSymbolAddress(&p_w1,  g_wt_w1);
    cudaGetSymbolAddress(&p_w2,  g_wt_w2);

    k_pos<<<1, 192>>>();
    k_bias<<<128, 128>>>(rpb);
    k_transpose<<<5760, 256>>>(qsw, qmw, pw, W1, W2);
    ln_partition<<<6144, 256>>>(x, n1w, n1b);
    gemm_mma<0><<<dim3(384, 9), 256, DSMEM>>>((const __nv_bfloat16*)p_xw,
        (const __nv_bfloat16*)p_wqs, qsb, (float*)p_qkv, 192, 576);
    attn_self<<<NWIN*8, 128>>>(mask);
    gemm_mma<0><<<dim3(384, 9), 256, DSMEM>>>((const __nv_bfloat16*)p_xm,
        (const __nv_bfloat16*)p_wqm, qmb, (float*)p_qkv, 192, 576);
    attn_mut<<<NWIN*8, 128>>>(mask);
    gemm_mma<0><<<dim3(384, 3), 256, DSMEM>>>((const __nv_bfloat16*)p_xout,
        (const __nv_bfloat16*)p_wp, pb, (float*)p_attn, 384, 192);
    resid_gate<<<6144, 256>>>(x, n2w, n2b, gw, gb);
    gemm_mma<1><<<dim3(384, 6, 8), 256, DSMEM>>>((const __nv_bfloat16*)p_xn2,
        (const __nv_bfloat16*)p_w1, b1, nullptr, 192, 384);
    gemm_mma<2><<<dim3(384, 3, 8), 256, DSMEM>>>((const __nv_bfloat16*)p_h,
        (const __nv_bfloat16*)p_w2, b2, nullptr, 384, 192);
    finalize<<<9216, 256>>>(out);
}